// round 12
// baseline (speedup 1.0000x reference)
#include <cuda_runtime.h>
#include <math.h>
#include <stdint.h>

#define Bb   8
#define Cch  128
#define Lsp  4096
#define CL   (Cch*Lsp)        // 524288
#define C4L  (4*CL)
#define BCL  (Bb*CL)

// ---------------- scratch (static device memory) ----------------------------
__device__ float g_y1[9*BCL];
__device__ float g_y2[9*BCL];
__device__ float g_q [BCL];
__device__ float g_KV[2*Bb*C4L];         // K: [B][4C][L] ; V^T: [B][L][4C]
__device__ float g_x [BCL];
__device__ float g_at [Bb*128*512];      // softmax probs
__device__ float g_atp[4*Bb*128*512];    // qk partials (4 L-parts)
__device__ uint2 g_Wpk[20*128*68];       // prepacked weights, interleaved (hi,lo)

__device__ __forceinline__ float gelu_exact(float x) {
    return 0.5f * x * (1.0f + erff(x * 0.70710678118654752f));
}

// ======================= bf16 hi/lo split-pack ==============================
__device__ __forceinline__ void packbf2(float x0, float x1, uint32_t& h, uint32_t& l) {
    asm("cvt.rn.bf16x2.f32 %0, %1, %2;" : "=r"(h) : "f"(x1), "f"(x0));
    float h0 = __uint_as_float(h << 16);
    float h1 = __uint_as_float(h & 0xffff0000u);
    asm("cvt.rn.bf16x2.f32 %0, %1, %2;" : "=r"(l) : "f"(x1 - h1), "f"(x0 - h0));
}

__device__ __forceinline__ void mmabf(float* d,
    uint32_t a0, uint32_t a1, uint32_t a2, uint32_t a3, uint32_t b0, uint32_t b1)
{
    asm volatile(
        "mma.sync.aligned.m16n8k16.row.col.f32.bf16.bf16.f32 "
        "{%0,%1,%2,%3}, {%4,%5,%6,%7}, {%8,%9}, {%0,%1,%2,%3};"
        : "+f"(d[0]), "+f"(d[1]), "+f"(d[2]), "+f"(d[3])
        : "r"(a0), "r"(a1), "r"(a2), "r"(a3), "r"(b0), "r"(b1));
}
__device__ __forceinline__ void mma3bf(float* d,
    const uint32_t* ah, const uint32_t* al,
    uint32_t bh0, uint32_t bh1, uint32_t bl0, uint32_t bl1)
{
    mmabf(d, ah[0], ah[1], ah[2], ah[3], bl0, bl1);
    mmabf(d, al[0], al[1], al[2], al[3], bh0, bh1);
    mmabf(d, ah[0], ah[1], ah[2], ah[3], bh0, bh1);
}

// ---------------------------------------------------------------------------
// Weight prepack: [o][c] fp32 -> [o][w] uint2 (hi,lo) with xor-swizzled w.
// ---------------------------------------------------------------------------
__global__ __launch_bounds__(256) void prep_w(
    const float* __restrict__ w1, const float* __restrict__ w2)
{
    const int mi = blockIdx.x;
    const float* src = mi < 10 ? w1 + (long)mi * 16384 : w2 + (long)(mi - 10) * 16384;
    uint2* dst = g_Wpk + (long)mi * 8704;
    const int tid = threadIdx.x;
#pragma unroll
    for (int i = 0; i < 16; i++) {
        int idx = tid + i * 256;            // 4096 float4
        int o = idx >> 5, c4 = idx & 31;
        float4 w = *(const float4*)&src[o * 128 + c4 * 4];
        uint32_t h0, l0, h1, l1;
        packbf2(w.x, w.y, h0, l0);
        packbf2(w.z, w.w, h1, l1);
        int wbase = (2 * c4) ^ ((o >> 1) & 2);
        dst[o * 68 + wbase]     = make_uint2(h0, l0);
        dst[o * 68 + wbase + 1] = make_uint2(h1, l1);
    }
    for (int i = tid; i < 512; i += 256) {  // zero pad w=64..67
        int o = i >> 2, w = 64 + (i & 3);
        dst[o * 68 + w] = make_uint2(0, 0);
    }
}

// ---------------------------------------------------------------------------
// Fused pointwise block: persistent over 8 x 64-token tiles, 256 thr, 2 CTA/SM.
// imode: 0 inq+b*CL | 1 (z==0?inq:mods[(z-1)&3])+b*CL | 2 inq+z*BCL+b*CL
// omode: 0 out0+b*CL | 1 out0+z*BCL+b*CL | 2 z==0->out0 (q); z1<4 K; z1>=4 V^T
// flags: bit0 in LN+GELU, bit1 out GELU, bit2 residual
// ---------------------------------------------------------------------------
#define STR2 68
#define AW2 (64*STR2)      // 4352 uint2
#define WW2 (128*STR2)     // 8704 uint2
#define CS_STR 132
#define PW_SMEM ((AW2 + WW2)*8 + (512 + 384)*4)   // 108032 B

__global__ __launch_bounds__(256, 2) void pw_v9(
    const float* __restrict__ inq,
    const float* __restrict__ mm0, const float* __restrict__ mm1,
    const float* __restrict__ mm2, const float* __restrict__ mm3,
    int imode, int wofs,
    const float* __restrict__ biasb,
    const float* __restrict__ g1b, const float* __restrict__ b1b,
    const float* __restrict__ g2b, const float* __restrict__ b2b,
    int blk0,
    const float* __restrict__ res,
    float* __restrict__ out0, float* __restrict__ out1, int omode,
    int flags)
{
    extern __shared__ uint2 sm2[];
    uint2* Asm = sm2;               // [64][STR2]
    uint2* Wsm = sm2 + AW2;         // [128][STR2]
    float* red = (float*)(sm2 + AW2 + WW2);   // [2][4][64]
    float* ps  = red + 512;                    // bias | go | bo
    float* Cs  = (float*)sm2;                  // epilogue alias (A region)

    const int tid = threadIdx.x;
    const int lane = tid & 31, wid = tid >> 5;
    const int gid = lane >> 2, tig = lane & 3;
    const int t = tid & 63, p = tid >> 6;
    const int cb = p * 32;
    const int b = blockIdx.y, z = blockIdx.z;
    const int blk = blk0 + z;
    const int xrA = (t >> 1) & 2;       // staging xor (row = token t)
    const int xf  = (gid >> 1) & 2;     // fragment xor (rows == gid mod 8 pattern)

    const float* src;
    if (imode == 0) src = inq;
    else if (imode == 1) {
        if (z == 0) src = inq;
        else { int zs = (z - 1) & 3; src = zs == 0 ? mm0 : zs == 1 ? mm1 : zs == 2 ? mm2 : mm3; }
    } else src = inq + (long)z * BCL;

    const float* bias = biasb + blk * 128;
    const float* gi = g1b + blk * 128, *bi = b1b + blk * 128;
    const float* go = g2b + blk * 128, *bo = b2b + blk * 128;

    // ---- W: flat uint4 copy from prepacked global ----
    {
        const uint4* wsrc = (const uint4*)(g_Wpk + (long)(wofs + blk) * 8704);
        uint4* wdst = (uint4*)Wsm;
#pragma unroll
        for (int i = 0; i < 17; i++)
            wdst[tid + i * 256] = wsrc[tid + i * 256];
    }
    if (tid < 128) { ps[tid] = bias[tid]; ps[128 + tid] = go[tid]; ps[256 + tid] = bo[tid]; }

    const int m0b = (wid >> 2) * 32, n0b = (wid & 3) * 32;
    const bool vtmode = (omode == 2 && z >= 5);

    for (int it = 0; it < 8; it++) {
        const int l0 = (blockIdx.x * 8 + it) * 64;
        const float* inp = src + (long)b * CL + l0;
        __syncthreads();   // protect red/Cs from previous iteration

        // ---- A loads: 4 threads per token, 32 channels ----
        float v[32];
        float s = 0.f, q = 0.f;
#pragma unroll
        for (int i = 0; i < 32; i++) {
            v[i] = inp[(long)(cb + i) * Lsp + t];
            s += v[i]; q += v[i] * v[i];
        }
        if (flags & 1) {
            red[p * 64 + t] = s; red[256 + p * 64 + t] = q;
            __syncthreads();
            float S = red[t] + red[64 + t] + red[128 + t] + red[192 + t];
            float Q = red[256 + t] + red[320 + t] + red[384 + t] + red[448 + t];
            float mean = S * (1.f / 128.f);
            float rstd = rsqrtf(Q * (1.f / 128.f) - mean * mean + 1e-6f);
#pragma unroll
            for (int j = 0; j < 8; j++) {
                float x0 = gelu_exact((v[4*j]   - mean) * rstd * gi[cb+4*j]   + bi[cb+4*j]);
                float x1 = gelu_exact((v[4*j+1] - mean) * rstd * gi[cb+4*j+1] + bi[cb+4*j+1]);
                float x2 = gelu_exact((v[4*j+2] - mean) * rstd * gi[cb+4*j+2] + bi[cb+4*j+2]);
                float x3 = gelu_exact((v[4*j+3] - mean) * rstd * gi[cb+4*j+3] + bi[cb+4*j+3]);
                uint32_t h0, l0w, h1, l1w;
                packbf2(x0, x1, h0, l0w); packbf2(x2, x3, h1, l1w);
                *(uint4*)&Asm[t * STR2 + ((p * 16 + 2 * j) ^ xrA)] =
                    make_uint4(h0, l0w, h1, l1w);
            }
        } else {
#pragma unroll
            for (int j = 0; j < 8; j++) {
                uint32_t h0, l0w, h1, l1w;
                packbf2(v[4*j], v[4*j+1], h0, l0w);
                packbf2(v[4*j+2], v[4*j+3], h1, l1w);
                *(uint4*)&Asm[t * STR2 + ((p * 16 + 2 * j) ^ xrA)] =
                    make_uint4(h0, l0w, h1, l1w);
            }
        }
        __syncthreads();

        // ---- mainloop: 16 LDS.64 + 24 MMA per k16 step ----
        float acc[8][4];
#pragma unroll
        for (int i = 0; i < 8; i++)
#pragma unroll
            for (int j = 0; j < 4; j++) acc[i][j] = 0.f;

#pragma unroll
        for (int k0 = 0; k0 < 128; k0 += 16) {
            const int kx = (k0 / 2 + tig) ^ xf;
            uint32_t bh[4][2], bl[4][2];
#pragma unroll
            for (int nt = 0; nt < 4; nt++) {
                int n = n0b + nt * 8 + gid;
                uint2 P0 = Wsm[n * STR2 + kx];
                uint2 P1 = Wsm[n * STR2 + kx + 4];
                bh[nt][0] = P0.x; bl[nt][0] = P0.y;
                bh[nt][1] = P1.x; bl[nt][1] = P1.y;
            }
#pragma unroll
            for (int mt = 0; mt < 2; mt++) {
                int r0 = m0b + mt * 16 + gid, r1 = r0 + 8;
                uint2 Pa = Asm[r0 * STR2 + kx];
                uint2 Pb = Asm[r1 * STR2 + kx];
                uint2 Pc = Asm[r0 * STR2 + kx + 4];
                uint2 Pd = Asm[r1 * STR2 + kx + 4];
                uint32_t ah[4] = {Pa.x, Pb.x, Pc.x, Pd.x};
                uint32_t al[4] = {Pa.y, Pb.y, Pc.y, Pd.y};
#pragma unroll
                for (int nt = 0; nt < 4; nt++)
                    mma3bf(acc[mt * 4 + nt], ah, al,
                           bh[nt][0], bh[nt][1], bl[nt][0], bl[nt][1]);
            }
        }
        __syncthreads();

        // ---- C -> smem (alias A region) ----
#pragma unroll
        for (int mt = 0; mt < 2; mt++)
#pragma unroll
            for (int nt = 0; nt < 4; nt++) {
                int m = m0b + mt * 16 + gid, n = n0b + nt * 8 + tig * 2;
                float* a = acc[mt * 4 + nt];
                *(float2*)&Cs[m * CS_STR + n] = make_float2(a[0], a[1]);
                *(float2*)&Cs[(m + 8) * CS_STR + n] = make_float2(a[2], a[3]);
            }
        __syncthreads();

        // ---- epilogue ----
        float w2[32];
        float s2 = 0.f, q2 = 0.f;
#pragma unroll
        for (int i = 0; i < 32; i++) {
            w2[i] = Cs[t * CS_STR + cb + i] + ps[cb + i];
            s2 += w2[i]; q2 += w2[i] * w2[i];
        }
        red[p * 64 + t] = s2; red[256 + p * 64 + t] = q2;
        __syncthreads();
        float S2 = red[t] + red[64 + t] + red[128 + t] + red[192 + t];
        float Q2 = red[256 + t] + red[320 + t] + red[384 + t] + red[448 + t];
        float mean2 = S2 * (1.f / 128.f);
        float rstd2 = rsqrtf(Q2 * (1.f / 128.f) - mean2 * mean2 + 1e-6f);
        const float* resp = (flags & 4) ? (res + (long)b * CL + l0) : nullptr;
        float buf[32];
#pragma unroll
        for (int i = 0; i < 32; i++) {
            int c = cb + i;
            float val = (w2[i] - mean2) * rstd2 * ps[128 + c] + ps[256 + c];
            if (flags & 2) val = gelu_exact(val);
            if (flags & 4) val += resp[(long)c * Lsp + t];
            buf[i] = val;
        }
        if (vtmode) {
            // V^T layout: [b][l][512], col offset (z-5)*128 + cb
            float* vp = out1 + (long)Bb * C4L + (long)b * ((long)Lsp * 512)
                      + (long)(l0 + t) * 512 + (z - 5) * 128 + cb;
#pragma unroll
            for (int j = 0; j < 8; j++)
                *(float4*)&vp[4 * j] = make_float4(buf[4*j], buf[4*j+1], buf[4*j+2], buf[4*j+3]);
        } else {
            float* outp;
            if (omode == 0) outp = out0 + (long)b * CL + l0;
            else if (omode == 1) outp = out0 + (long)z * BCL + (long)b * CL + l0;
            else if (z == 0) outp = out0 + (long)b * CL + l0;
            else outp = out1 + (long)(z - 1) * CL + (long)b * C4L + l0;   // K layout
#pragma unroll
            for (int i = 0; i < 32; i++)
                outp[(long)(cb + i) * Lsp + t] = buf[i];
        }
    }
}

// ---------------------------------------------------------------------------
// qk partial: 64c x 128k tile, packed interleaved + LDS.64 mainloop.
// grid (4 kt, 4 lp, 16 = b*2+ct)
// ---------------------------------------------------------------------------
#define QK_SMEM ((AW2 + WW2)*8)   // 104448 B
__global__ __launch_bounds__(256, 2) void qk_v9(
    const float* __restrict__ q, const float* __restrict__ K,
    float* __restrict__ atp)
{
    extern __shared__ uint2 sm2[];
    uint2* Qs = sm2;               // [64][STR2]
    uint2* Ks = sm2 + AW2;         // [128][STR2]
    const int tid = threadIdx.x;
    const int lane = tid & 31, wid = tid >> 5;
    const int gid = lane >> 2, tig = lane & 3;
    const int kt = blockIdx.x * 128, lp = blockIdx.y;
    const int b = blockIdx.z >> 1, ct = blockIdx.z & 1;
    const int c0 = ct * 64;
    const float* qp = q + (long)b * CL + (long)c0 * Lsp;
    const float* Kp = K + (long)b * C4L + (long)kt * Lsp;
    const int lbase = lp * 1024;
    const int xf = (gid >> 1) & 2;

    const int m0b = (wid >> 2) * 32, n0b = (wid & 3) * 32;
    float acc[8][4];
#pragma unroll
    for (int i = 0; i < 8; i++)
#pragma unroll
        for (int j = 0; j < 4; j++) acc[i][j] = 0.f;

    for (int lc = 0; lc < 1024; lc += 128) {
        const int l0 = lbase + lc;
        __syncthreads();
#pragma unroll
        for (int j = 0; j < 8; j++) {          // Q: 64 rows x 32 float4
            int idx = tid + j * 256;
            int r = idx >> 5, c4 = idx & 31;
            float4 a = *(const float4*)&qp[(long)r * Lsp + l0 + c4 * 4];
            uint32_t h0, l0w, h1, l1w;
            packbf2(a.x, a.y, h0, l0w); packbf2(a.z, a.w, h1, l1w);
            *(uint4*)&Qs[r * STR2 + ((2 * c4) ^ ((r >> 1) & 2))] =
                make_uint4(h0, l0w, h1, l1w);
        }
#pragma unroll
        for (int j = 0; j < 16; j++) {         // K: 128 rows x 32 float4
            int idx = tid + j * 256;
            int r = idx >> 5, c4 = idx & 31;
            float4 kk = *(const float4*)&Kp[(long)r * Lsp + l0 + c4 * 4];
            uint32_t h0, l0w, h1, l1w;
            packbf2(kk.x, kk.y, h0, l0w); packbf2(kk.z, kk.w, h1, l1w);
            *(uint4*)&Ks[r * STR2 + ((2 * c4) ^ ((r >> 1) & 2))] =
                make_uint4(h0, l0w, h1, l1w);
        }
        __syncthreads();
#pragma unroll
        for (int k0 = 0; k0 < 128; k0 += 16) {
            const int kx = (k0 / 2 + tig) ^ xf;
            uint32_t bh[4][2], bl[4][2];
#pragma unroll
            for (int nt = 0; nt < 4; nt++) {
                int n = n0b + nt * 8 + gid;
                uint2 P0 = Ks[n * STR2 + kx];
                uint2 P1 = Ks[n * STR2 + kx + 4];
                bh[nt][0] = P0.x; bl[nt][0] = P0.y;
                bh[nt][1] = P1.x; bl[nt][1] = P1.y;
            }
#pragma unroll
            for (int mt = 0; mt < 2; mt++) {
                int r0 = m0b + mt * 16 + gid, r1 = r0 + 8;
                uint2 Pa = Qs[r0 * STR2 + kx];
                uint2 Pb = Qs[r1 * STR2 + kx];
                uint2 Pc = Qs[r0 * STR2 + kx + 4];
                uint2 Pd = Qs[r1 * STR2 + kx + 4];
                uint32_t ah[4] = {Pa.x, Pb.x, Pc.x, Pd.x};
                uint32_t al[4] = {Pa.y, Pb.y, Pc.y, Pd.y};
#pragma unroll
                for (int nt = 0; nt < 4; nt++)
                    mma3bf(acc[mt * 4 + nt], ah, al,
                           bh[nt][0], bh[nt][1], bl[nt][0], bl[nt][1]);
            }
        }
    }
    float* ap = atp + (long)lp * (Bb * 65536) + (long)b * 65536 + (long)c0 * 512;
#pragma unroll
    for (int mt = 0; mt < 2; mt++)
#pragma unroll
        for (int nt = 0; nt < 4; nt++) {
            int m = m0b + mt * 16 + gid;
            int n = kt + n0b + nt * 8 + tig * 2;
            float* a = acc[mt * 4 + nt];
            *(float2*)&ap[(long)m * 512 + n] = make_float2(a[0], a[1]);
            *(float2*)&ap[(long)(m + 8) * 512 + n] = make_float2(a[2], a[3]);
        }
}

// ---------------------------------------------------------------------------
// masked softmax: sums 4 qk partials, scales by 1/64, writes probs
// ---------------------------------------------------------------------------
__global__ __launch_bounds__(128) void softmax_v6(
    const float* __restrict__ atp, float* __restrict__ at,
    const int* __restrict__ mask)
{
    __shared__ float sm[128];
    const int row = blockIdx.x;
    const int b = row >> 7;
    const int t = threadIdx.x;
    const float sc = 0.015625f;
    const long roff = (long)row * 512;
    const long pstr = (long)Bb * 65536;

    float v[4];
    float mx = -INFINITY;
#pragma unroll
    for (int j = 0; j < 4; j++) {
        bool on = mask[b * 4 + j] > 0;
        float sum = atp[roff + j * 128 + t] + atp[pstr + roff + j * 128 + t]
                  + atp[2 * pstr + roff + j * 128 + t] + atp[3 * pstr + roff + j * 128 + t];
        v[j] = on ? sum * sc : -INFINITY;
        mx = fmaxf(mx, v[j]);
    }
    sm[t] = mx; __syncthreads();
    for (int s = 64; s > 0; s >>= 1) {
        if (t < s) sm[t] = fmaxf(sm[t], sm[t + s]);
        __syncthreads();
    }
    mx = sm[0]; __syncthreads();

    float sum = 0.f;
#pragma unroll
    for (int j = 0; j < 4; j++) {
        v[j] = (v[j] == -INFINITY) ? 0.f : expf(v[j] - mx);
        sum += v[j];
    }
    sm[t] = sum; __syncthreads();
    for (int s = 64; s > 0; s >>= 1) {
        if (t < s) sm[t] += sm[t + s];
        __syncthreads();
    }
    float inv = 1.f / sm[0];
#pragma unroll
    for (int j = 0; j < 4; j++) at[roff + j * 128 + t] = v[j] * inv;
}

// ---------------------------------------------------------------------------
// av: x[b][c][lt+n] = sum_k attn[b][c][k] * V^T[b][lt+n][k]
// packed-bf16, tile m128c x n64l, k-chunks 64. grid (64, Bb)
// ---------------------------------------------------------------------------
#define ASTR 36
#define AV_A2 (128*ASTR)
#define AV_B2 (64*ASTR)
#define AV_SMEM ((AV_A2 + AV_B2)*8)   // 55296 B
__global__ __launch_bounds__(256, 2) void av_v9(
    const float* __restrict__ at, const float* __restrict__ vT,
    float* __restrict__ xout)
{
    extern __shared__ uint2 sm2[];
    uint2* Aa = sm2;               // attn [128][ASTR]
    uint2* Vs = sm2 + AV_A2;       // V^T  [64][ASTR]
    const int tid = threadIdx.x;
    const int lane = tid & 31, wid = tid >> 5;
    const int gid = lane >> 2, tig = lane & 3;
    const int lt = blockIdx.x * 64;
    const int b = blockIdx.y;
    const float* ap = at + (long)b * 65536;
    const float* vp = vT + (long)b * ((long)Lsp * 512);
    const int xf = (gid >> 1) & 2;

    const int m0b = (wid >> 1) * 32, n0b = (wid & 1) * 32;
    float acc[8][4];
#pragma unroll
    for (int i = 0; i < 8; i++)
#pragma unroll
        for (int j = 0; j < 4; j++) acc[i][j] = 0.f;

    for (int kg = 0; kg < 512; kg += 64) {
        __syncthreads();
#pragma unroll
        for (int j = 0; j < 8; j++) {       // attn: 128 rows x 16 f4
            int idx = tid + j * 256;
            int r = idx >> 4, c4 = idx & 15;
            float4 a = *(const float4*)&ap[(long)r * 512 + kg + c4 * 4];
            uint32_t h0, l0w, h1, l1w;
            packbf2(a.x, a.y, h0, l0w); packbf2(a.z, a.w, h1, l1w);
            *(uint4*)&Aa[r * ASTR + ((2 * c4) ^ ((r >> 1) & 2))] =
                make_uint4(h0, l0w, h1, l1w);
        }
#pragma unroll
        for (int j = 0; j < 4; j++) {       // V^T: 64 rows x 16 f4
            int idx = tid + j * 256;
            int r = idx >> 4, c4 = idx & 15;
            float4 vv = *(const float4*)&vp[(long)(lt + r) * 512 + kg + c4 * 4];
            uint32_t h0, l0w, h1, l1w;
            packbf2(vv.x, vv.y, h0, l0w); packbf2(vv.z, vv.w, h1, l1w);
            *(uint4*)&Vs[r * ASTR + ((2 * c4) ^ ((r >> 1) & 2))] =
                make_uint4(h0, l0w, h1, l1w);
        }
        __syncthreads();
#pragma unroll
        for (int k0 = 0; k0 < 64; k0 += 16) {
            const int kx = (k0 / 2 + tig) ^ xf;
            uint32_t bh[4][2], bl[4][2];
#pragma unroll
            for (int nt = 0; nt < 4; nt++) {
                int n = n0b + nt * 8 + gid;
                uint2 P0 = Vs[n * ASTR + kx];
                uint2 P1 = Vs[n * ASTR + kx + 4];
                bh[nt][0] = P0.x; bl[nt][0] = P0.y;
                bh[nt][1] = P1.x; bl[nt][1] = P1.y;
            }
#pragma unroll
            for (int mt = 0; mt < 2; mt++) {
                int r0 = m0b + mt * 16 + gid, r1 = r0 + 8;
                uint2 Pa = Aa[r0 * ASTR + kx];
                uint2 Pb = Aa[r1 * ASTR + kx];
                uint2 Pc = Aa[r0 * ASTR + kx + 4];
                uint2 Pd = Aa[r1 * ASTR + kx + 4];
                uint32_t ah[4] = {Pa.x, Pb.x, Pc.x, Pd.x};
                uint32_t al[4] = {Pa.y, Pb.y, Pc.y, Pd.y};
#pragma unroll
                for (int nt = 0; nt < 4; nt++)
                    mma3bf(acc[mt * 4 + nt], ah, al,
                           bh[nt][0], bh[nt][1], bl[nt][0], bl[nt][1]);
            }
        }
    }
    float* xp = xout + (long)b * CL + lt;
#pragma unroll
    for (int mt = 0; mt < 2; mt++)
#pragma unroll
        for (int nt = 0; nt < 4; nt++) {
            int m = m0b + mt * 16 + gid;
            int n = n0b + nt * 8 + tig * 2;
            float* a = acc[mt * 4 + nt];
            *(float2*)&xp[(long)m * Lsp + n] = make_float2(a[0], a[1]);
            *(float2*)&xp[(long)(m + 8) * Lsp + n] = make_float2(a[2], a[3]);
        }
}

// ---------------------------------------------------------------------------
// Depthwise 3x3x3 + bias, float4 loads
// ---------------------------------------------------------------------------
__global__ __launch_bounds__(256) void dw_v3(
    const float* __restrict__ inb, float* __restrict__ outb,
    long iz, long ib,
    const float* __restrict__ w27b, const float* __restrict__ biasb, int blk0)
{
    __shared__ float sp[16 * 324];
    const int tid = threadIdx.x;
    const int x = tid & 15, y = tid >> 4;
    const int c = blockIdx.x, b = blockIdx.y, z = blockIdx.z;
    const int blk = blk0 + z;

    const float* in = inb + (long)z * iz + (long)b * ib + (long)c * Lsp;
    float* out = outb + (long)z * iz + (long)b * ib + (long)c * Lsp;
    const float* wv = w27b + (long)blk * Cch * 27 + c * 27;
    const float bias = biasb[blk * Cch + c];

    for (int idx = tid; idx < 16 * 324; idx += 256) sp[idx] = 0.f;
    __syncthreads();
    const float4* in4 = (const float4*)in;
#pragma unroll
    for (int j = 0; j < 4; j++) {
        int i4 = tid + j * 256;
        float4 vv = in4[i4];
        int zz = i4 >> 6, rem = i4 & 63;
        float* dst = &sp[zz * 324 + ((rem >> 2) + 1) * 18 + (rem & 3) * 4 + 1];
        dst[0] = vv.x; dst[1] = vv.y; dst[2] = vv.z; dst[3] = vv.w;
    }
    float w[27];
#pragma unroll
    for (int k = 0; k < 27; k++) w[k] = wv[k];
    __syncthreads();

    float p0[9], p1[9], p2[9];
#pragma unroll
    for (int k = 0; k < 9; k++) p0[k] = 0.f;
#pragma unroll
    for (int dy = 0; dy < 3; dy++)
#pragma unroll
        for (int dx = 0; dx < 3; dx++)
            p1[dy * 3 + dx] = sp[(y + dy) * 18 + (x + dx)];

#pragma unroll
    for (int zz = 0; zz < 16; zz++) {
        if (zz < 15) {
#pragma unroll
            for (int dy = 0; dy < 3; dy++)
#pragma unroll
                for (int dx = 0; dx < 3; dx++)
                    p2[dy * 3 + dx] = sp[(zz + 1) * 324 + (y + dy) * 18 + (x + dx)];
        } else {
#pragma unroll
            for (int k = 0; k < 9; k++) p2[k] = 0.f;
        }
        float a = bias;
#pragma unroll
        for (int k = 0; k < 9; k++) a += p0[k] * w[k];
#pragma unroll
        for (int k = 0; k < 9; k++) a += p1[k] * w[9 + k];
#pragma unroll
        for (int k = 0; k < 9; k++) a += p2[k] * w[18 + k];
        out[zz * 256 + tid] = a;
#pragma unroll
        for (int k = 0; k < 9; k++) { p0[k] = p1[k]; p1[k] = p2[k]; }
    }
}

// ---------------------------------------------------------------------------
extern "C" void kernel_launch(void* const* d_in, const int* in_sizes, int n_in,
                              void* d_out, int out_size)
{
    const float* query = (const float*)d_in[0];
    const float* m0 = (const float*)d_in[1];
    const float* m1 = (const float*)d_in[2];
    const float* m2 = (const float*)d_in[3];
    const float* m3 = (const float*)d_in[4];
    const int*   mask  = (const int*)d_in[5];
    const float* pw1_w = (const float*)d_in[6];
    const float* pw1_b = (const float*)d_in[7];
    const float* ln1_g = (const float*)d_in[8];
    const float* ln1_b = (const float*)d_in[9];
    const float* dw_w  = (const float*)d_in[10];
    const float* dw_b  = (const float*)d_in[11];
    const float* ln2_g = (const float*)d_in[12];
    const float* ln2_b = (const float*)d_in[13];
    const float* pw2_w = (const float*)d_in[14];
    const float* pw2_b = (const float*)d_in[15];
    const float* ln3_g = (const float*)d_in[16];
    const float* ln3_b = (const float*)d_in[17];
    float* out = (float*)d_out;

    float *y1, *y2, *qb, *kv, *xb, *at, *atp;
    cudaGetSymbolAddress((void**)&y1, g_y1);
    cudaGetSymbolAddress((void**)&y2, g_y2);
    cudaGetSymbolAddress((void**)&qb, g_q);
    cudaGetSymbolAddress((void**)&kv, g_KV);
    cudaGetSymbolAddress((void**)&xb, g_x);
    cudaGetSymbolAddress((void**)&at, g_at);
    cudaGetSymbolAddress((void**)&atp, g_atp);
    float* Kb = kv;
    float* Vt = kv + (long)Bb * C4L;

    cudaFuncSetAttribute(pw_v9, cudaFuncAttributeMaxDynamicSharedMemorySize, PW_SMEM);
    cudaFuncSetAttribute(qk_v9, cudaFuncAttributeMaxDynamicSharedMemorySize, QK_SMEM);
    cudaFuncSetAttribute(av_v9, cudaFuncAttributeMaxDynamicSharedMemorySize, AV_SMEM);

    // ---- weight prepack (packed bf16 hi/lo, swizzled) ----
    prep_w<<<20, 256>>>(pw1_w, pw2_w);

    // ---- blocks 0..8 (query + K/V maps) ----
    pw_v9<<<dim3(8, Bb, 9), 256, PW_SMEM>>>(
        query, m0, m1, m2, m3, /*imode=*/1, /*wofs=*/0,
        pw1_b, ln1_g, ln1_b, ln1_g, ln1_b, /*blk0=*/0,
        nullptr, y1, nullptr, /*omode=*/1, /*flags=*/2);
    dw_v3<<<dim3(Cch, Bb, 9), 256>>>(y1, y2, BCL, CL, dw_w, dw_b, 0);
    pw_v9<<<dim3(8, Bb, 9), 256, PW_SMEM>>>(
        y2, nullptr, nullptr, nullptr, nullptr, /*imode=*/2, /*wofs=*/10,
        pw2_b, ln2_g, ln2_b, ln3_g, ln3_b, /*blk0=*/0,
        nullptr, qb, kv, /*omode=*/2, /*flags=*/1);

    // ---- attention ----
    qk_v9<<<dim3(4, 4, 16), 256, QK_SMEM>>>(qb, Kb, atp);
    softmax_v6<<<Bb * 128, 128>>>(atp, at, mask);
    av_v9<<<dim3(64, Bb), 256, AV_SMEM>>>(at, Vt, xb);

    // ---- out_project (blk 9) + residual ----
    pw_v9<<<dim3(8, Bb, 1), 256, PW_SMEM>>>(
        xb, nullptr, nullptr, nullptr, nullptr, /*imode=*/0, /*wofs=*/0,
        pw1_b, ln1_g, ln1_b, ln1_g, ln1_b, /*blk0=*/9,
        nullptr, y1, nullptr, /*omode=*/0, /*flags=*/2);
    dw_v3<<<dim3(Cch, Bb, 1), 256>>>(y1, y2, BCL, CL, dw_w, dw_b, 9);
    pw_v9<<<dim3(8, Bb, 1), 256, PW_SMEM>>>(
        y2, nullptr, nullptr, nullptr, nullptr, /*imode=*/0, /*wofs=*/10,
        pw2_b, ln2_g, ln2_b, ln3_g, ln3_b, /*blk0=*/9,
        query, out, nullptr, /*omode=*/0, /*flags=*/1 | 4);
}

// round 13
// speedup vs baseline: 1.1775x; 1.1775x over previous
#include <cuda_runtime.h>
#include <math.h>
#include <stdint.h>

#define Bb   8
#define Cch  128
#define Lsp  4096
#define CL   (Cch*Lsp)        // 524288
#define C4L  (4*CL)
#define BCL  (Bb*CL)

// ---------------- scratch (static device memory) ----------------------------
__device__ float g_y1[9*BCL];
__device__ float g_y2[9*BCL];
__device__ float g_q [BCL];
__device__ float g_KV[2*Bb*C4L];         // K: [B][4C][L] ; V^T: [B][L][4C]
__device__ float g_x [BCL];
__device__ float g_at [Bb*128*512];      // softmax probs
__device__ float g_atp[4*Bb*128*512];    // qk partials (4 L-parts)
__device__ uint2 g_Wpk[20*128*68];       // prepacked weights, interleaved (hi,lo)

__device__ __forceinline__ float gelu_exact(float x) {
    return 0.5f * x * (1.0f + erff(x * 0.70710678118654752f));
}

// ======================= bf16 hi/lo split-pack ==============================
__device__ __forceinline__ void packbf2(float x0, float x1, uint32_t& h, uint32_t& l) {
    asm("cvt.rn.bf16x2.f32 %0, %1, %2;" : "=r"(h) : "f"(x1), "f"(x0));
    float h0 = __uint_as_float(h << 16);
    float h1 = __uint_as_float(h & 0xffff0000u);
    asm("cvt.rn.bf16x2.f32 %0, %1, %2;" : "=r"(l) : "f"(x1 - h1), "f"(x0 - h0));
}

__device__ __forceinline__ void mmabf(float* d,
    uint32_t a0, uint32_t a1, uint32_t a2, uint32_t a3, uint32_t b0, uint32_t b1)
{
    asm volatile(
        "mma.sync.aligned.m16n8k16.row.col.f32.bf16.bf16.f32 "
        "{%0,%1,%2,%3}, {%4,%5,%6,%7}, {%8,%9}, {%0,%1,%2,%3};"
        : "+f"(d[0]), "+f"(d[1]), "+f"(d[2]), "+f"(d[3])
        : "r"(a0), "r"(a1), "r"(a2), "r"(a3), "r"(b0), "r"(b1));
}
__device__ __forceinline__ void mma3bf(float* d,
    const uint32_t* ah, const uint32_t* al,
    uint32_t bh0, uint32_t bh1, uint32_t bl0, uint32_t bl1)
{
    mmabf(d, ah[0], ah[1], ah[2], ah[3], bl0, bl1);
    mmabf(d, al[0], al[1], al[2], al[3], bh0, bh1);
    mmabf(d, ah[0], ah[1], ah[2], ah[3], bh0, bh1);
}

// ---------------------------------------------------------------------------
// Weight prepack: [o][c] fp32 -> [o][w] uint2 (hi,lo) with xor-swizzled w.
// ---------------------------------------------------------------------------
__global__ __launch_bounds__(256) void prep_w(
    const float* __restrict__ w1, const float* __restrict__ w2)
{
    const int mi = blockIdx.x;
    const float* src = mi < 10 ? w1 + (long)mi * 16384 : w2 + (long)(mi - 10) * 16384;
    uint2* dst = g_Wpk + (long)mi * 8704;
    const int tid = threadIdx.x;
#pragma unroll
    for (int i = 0; i < 16; i++) {
        int idx = tid + i * 256;            // 4096 float4
        int o = idx >> 5, c4 = idx & 31;
        float4 w = *(const float4*)&src[o * 128 + c4 * 4];
        uint32_t h0, l0, h1, l1;
        packbf2(w.x, w.y, h0, l0);
        packbf2(w.z, w.w, h1, l1);
        int wbase = (2 * c4) ^ ((o >> 1) & 2);
        dst[o * 68 + wbase]     = make_uint2(h0, l0);
        dst[o * 68 + wbase + 1] = make_uint2(h1, l1);
    }
    for (int i = tid; i < 512; i += 256) {  // zero pad w=64..67
        int o = i >> 2, w = 64 + (i & 3);
        dst[o * 68 + w] = make_uint2(0, 0);
    }
}

// ---------------------------------------------------------------------------
// Fused pointwise block: ONE 64-token x 128-out tile per CTA, 256 thr, 2 CTA/SM.
// W staged as flat uint4 copy from prepacked global (zero conversions).
// imode: 0 inq+b*CL | 1 (z==0?inq:mods[(z-1)&3])+b*CL | 2 inq+z*BCL+b*CL
// omode: 0 out0+b*CL | 1 out0+z*BCL+b*CL | 2 z==0->out0 (q); z1<4 K; z1>=4 V^T
// flags: bit0 in LN+GELU, bit1 out GELU, bit2 residual
// ---------------------------------------------------------------------------
#define STR2 68
#define AW2 (64*STR2)      // 4352 uint2
#define WW2 (128*STR2)     // 8704 uint2
#define CS_STR 132
#define PW_SMEM ((AW2 + WW2)*8 + (512 + 384)*4)   // 108032 B

__global__ __launch_bounds__(256, 2) void pw_v10(
    const float* __restrict__ inq,
    const float* __restrict__ mm0, const float* __restrict__ mm1,
    const float* __restrict__ mm2, const float* __restrict__ mm3,
    int imode, int wofs,
    const float* __restrict__ biasb,
    const float* __restrict__ g1b, const float* __restrict__ b1b,
    const float* __restrict__ g2b, const float* __restrict__ b2b,
    int blk0,
    const float* __restrict__ res,
    float* __restrict__ out0, float* __restrict__ out1, int omode,
    int flags)
{
    extern __shared__ uint2 sm2[];
    uint2* Asm = sm2;               // [64][STR2]
    uint2* Wsm = sm2 + AW2;         // [128][STR2]
    float* red = (float*)(sm2 + AW2 + WW2);   // [2][4][64]
    float* ps  = red + 512;                    // bias | go | bo
    float* Cs  = (float*)sm2;                  // epilogue alias (A region)

    const int tid = threadIdx.x;
    const int lane = tid & 31, wid = tid >> 5;
    const int gid = lane >> 2, tig = lane & 3;
    const int t = tid & 63, p = tid >> 6;
    const int cb = p * 32;
    const int b = blockIdx.y, z = blockIdx.z;
    const int l0 = blockIdx.x * 64;
    const int blk = blk0 + z;
    const int xrA = (t >> 1) & 2;
    const int xf  = (gid >> 1) & 2;

    const float* src;
    if (imode == 0) src = inq;
    else if (imode == 1) {
        if (z == 0) src = inq;
        else { int zs = (z - 1) & 3; src = zs == 0 ? mm0 : zs == 1 ? mm1 : zs == 2 ? mm2 : mm3; }
    } else src = inq + (long)z * BCL;
    const float* inp = src + (long)b * CL + l0;

    const float* bias = biasb + blk * 128;
    const float* gi = g1b + blk * 128, *bi = b1b + blk * 128;
    const float* go = g2b + blk * 128, *bo = b2b + blk * 128;

    // ---- A loads: 4 threads per token, 32 channels each ----
    float v[32];
    float s = 0.f, q = 0.f;
#pragma unroll
    for (int i = 0; i < 32; i++) {
        v[i] = inp[(long)(cb + i) * Lsp + t];
        s += v[i]; q += v[i] * v[i];
    }
    // ---- W: flat uint4 copy from prepacked global ----
    {
        const uint4* wsrc = (const uint4*)(g_Wpk + (long)(wofs + blk) * 8704);
        uint4* wdst = (uint4*)Wsm;
#pragma unroll
        for (int i = 0; i < 17; i++)
            wdst[tid + i * 256] = wsrc[tid + i * 256];
    }
    if (tid < 128) { ps[tid] = bias[tid]; ps[128 + tid] = go[tid]; ps[256 + tid] = bo[tid]; }

    if (flags & 1) {
        red[p * 64 + t] = s; red[256 + p * 64 + t] = q;
        __syncthreads();
        float S = red[t] + red[64 + t] + red[128 + t] + red[192 + t];
        float Q = red[256 + t] + red[320 + t] + red[384 + t] + red[448 + t];
        float mean = S * (1.f / 128.f);
        float rstd = rsqrtf(Q * (1.f / 128.f) - mean * mean + 1e-6f);
#pragma unroll
        for (int j = 0; j < 8; j++) {
            float x0 = gelu_exact((v[4*j]   - mean) * rstd * gi[cb+4*j]   + bi[cb+4*j]);
            float x1 = gelu_exact((v[4*j+1] - mean) * rstd * gi[cb+4*j+1] + bi[cb+4*j+1]);
            float x2 = gelu_exact((v[4*j+2] - mean) * rstd * gi[cb+4*j+2] + bi[cb+4*j+2]);
            float x3 = gelu_exact((v[4*j+3] - mean) * rstd * gi[cb+4*j+3] + bi[cb+4*j+3]);
            uint32_t h0, l0w, h1, l1w;
            packbf2(x0, x1, h0, l0w); packbf2(x2, x3, h1, l1w);
            *(uint4*)&Asm[t * STR2 + ((p * 16 + 2 * j) ^ xrA)] =
                make_uint4(h0, l0w, h1, l1w);
        }
    } else {
#pragma unroll
        for (int j = 0; j < 8; j++) {
            uint32_t h0, l0w, h1, l1w;
            packbf2(v[4*j], v[4*j+1], h0, l0w);
            packbf2(v[4*j+2], v[4*j+3], h1, l1w);
            *(uint4*)&Asm[t * STR2 + ((p * 16 + 2 * j) ^ xrA)] =
                make_uint4(h0, l0w, h1, l1w);
        }
    }
    __syncthreads();

    // ---- mainloop: 16 LDS.64 + 24 MMA per k16 step ----
    const int m0b = (wid >> 2) * 32, n0b = (wid & 3) * 32;
    float acc[8][4];
#pragma unroll
    for (int i = 0; i < 8; i++)
#pragma unroll
        for (int j = 0; j < 4; j++) acc[i][j] = 0.f;

#pragma unroll
    for (int k0 = 0; k0 < 128; k0 += 16) {
        const int kx = (k0 / 2 + tig) ^ xf;
        uint32_t bh[4][2], bl[4][2];
#pragma unroll
        for (int nt = 0; nt < 4; nt++) {
            int n = n0b + nt * 8 + gid;
            uint2 P0 = Wsm[n * STR2 + kx];
            uint2 P1 = Wsm[n * STR2 + kx + 4];
            bh[nt][0] = P0.x; bl[nt][0] = P0.y;
            bh[nt][1] = P1.x; bl[nt][1] = P1.y;
        }
#pragma unroll
        for (int mt = 0; mt < 2; mt++) {
            int r0 = m0b + mt * 16 + gid, r1 = r0 + 8;
            uint2 Pa = Asm[r0 * STR2 + kx];
            uint2 Pb = Asm[r1 * STR2 + kx];
            uint2 Pc = Asm[r0 * STR2 + kx + 4];
            uint2 Pd = Asm[r1 * STR2 + kx + 4];
            uint32_t ah[4] = {Pa.x, Pb.x, Pc.x, Pd.x};
            uint32_t al[4] = {Pa.y, Pb.y, Pc.y, Pd.y};
#pragma unroll
            for (int nt = 0; nt < 4; nt++)
                mma3bf(acc[mt * 4 + nt], ah, al,
                       bh[nt][0], bh[nt][1], bl[nt][0], bl[nt][1]);
        }
    }
    __syncthreads();

    // ---- C -> smem (alias A region) ----
#pragma unroll
    for (int mt = 0; mt < 2; mt++)
#pragma unroll
        for (int nt = 0; nt < 4; nt++) {
            int m = m0b + mt * 16 + gid, n = n0b + nt * 8 + tig * 2;
            float* a = acc[mt * 4 + nt];
            *(float2*)&Cs[m * CS_STR + n] = make_float2(a[0], a[1]);
            *(float2*)&Cs[(m + 8) * CS_STR + n] = make_float2(a[2], a[3]);
        }
    __syncthreads();

    // ---- epilogue: +bias -> LN -> [GELU] -> [res] ----
    float w2[32];
    float s2 = 0.f, q2 = 0.f;
#pragma unroll
    for (int i = 0; i < 32; i++) {
        w2[i] = Cs[t * CS_STR + cb + i] + ps[cb + i];
        s2 += w2[i]; q2 += w2[i] * w2[i];
    }
    red[p * 64 + t] = s2; red[256 + p * 64 + t] = q2;
    __syncthreads();
    float S2 = red[t] + red[64 + t] + red[128 + t] + red[192 + t];
    float Q2 = red[256 + t] + red[320 + t] + red[384 + t] + red[448 + t];
    float mean2 = S2 * (1.f / 128.f);
    float rstd2 = rsqrtf(Q2 * (1.f / 128.f) - mean2 * mean2 + 1e-6f);
    const float* resp = (flags & 4) ? (res + (long)b * CL + l0) : nullptr;
    float buf[32];
#pragma unroll
    for (int i = 0; i < 32; i++) {
        int c = cb + i;
        float val = (w2[i] - mean2) * rstd2 * ps[128 + c] + ps[256 + c];
        if (flags & 2) val = gelu_exact(val);
        if (flags & 4) val += resp[(long)c * Lsp + t];
        buf[i] = val;
    }
    if (omode == 2 && z >= 5) {
        // V^T layout: [b][l][512], col offset (z-5)*128 + cb
        float* vp = out1 + (long)Bb * C4L + (long)b * ((long)Lsp * 512)
                  + (long)(l0 + t) * 512 + (z - 5) * 128 + cb;
#pragma unroll
        for (int j = 0; j < 8; j++)
            *(float4*)&vp[4 * j] = make_float4(buf[4*j], buf[4*j+1], buf[4*j+2], buf[4*j+3]);
    } else {
        float* outp;
        if (omode == 0) outp = out0 + (long)b * CL + l0;
        else if (omode == 1) outp = out0 + (long)z * BCL + (long)b * CL + l0;
        else if (z == 0) outp = out0 + (long)b * CL + l0;
        else outp = out1 + (long)(z - 1) * CL + (long)b * C4L + l0;   // K layout
#pragma unroll
        for (int i = 0; i < 32; i++)
            outp[(long)(cb + i) * Lsp + t] = buf[i];
    }
}

// ---------------------------------------------------------------------------
// qk partial: 64c x 128k tile, packed interleaved + LDS.64 mainloop.
// grid (4 kt, 4 lp, 16 = b*2+ct)
// ---------------------------------------------------------------------------
#define QK_SMEM ((AW2 + WW2)*8)   // 104448 B
__global__ __launch_bounds__(256, 2) void qk_v9(
    const float* __restrict__ q, const float* __restrict__ K,
    float* __restrict__ atp)
{
    extern __shared__ uint2 sm2[];
    uint2* Qs = sm2;               // [64][STR2]
    uint2* Ks = sm2 + AW2;         // [128][STR2]
    const int tid = threadIdx.x;
    const int lane = tid & 31, wid = tid >> 5;
    const int gid = lane >> 2, tig = lane & 3;
    const int kt = blockIdx.x * 128, lp = blockIdx.y;
    const int b = blockIdx.z >> 1, ct = blockIdx.z & 1;
    const int c0 = ct * 64;
    const float* qp = q + (long)b * CL + (long)c0 * Lsp;
    const float* Kp = K + (long)b * C4L + (long)kt * Lsp;
    const int lbase = lp * 1024;
    const int xf = (gid >> 1) & 2;

    const int m0b = (wid >> 2) * 32, n0b = (wid & 3) * 32;
    float acc[8][4];
#pragma unroll
    for (int i = 0; i < 8; i++)
#pragma unroll
        for (int j = 0; j < 4; j++) acc[i][j] = 0.f;

    for (int lc = 0; lc < 1024; lc += 128) {
        const int l0 = lbase + lc;
        __syncthreads();
#pragma unroll
        for (int j = 0; j < 8; j++) {          // Q: 64 rows x 32 float4
            int idx = tid + j * 256;
            int r = idx >> 5, c4 = idx & 31;
            float4 a = *(const float4*)&qp[(long)r * Lsp + l0 + c4 * 4];
            uint32_t h0, l0w, h1, l1w;
            packbf2(a.x, a.y, h0, l0w); packbf2(a.z, a.w, h1, l1w);
            *(uint4*)&Qs[r * STR2 + ((2 * c4) ^ ((r >> 1) & 2))] =
                make_uint4(h0, l0w, h1, l1w);
        }
#pragma unroll
        for (int j = 0; j < 16; j++) {         // K: 128 rows x 32 float4
            int idx = tid + j * 256;
            int r = idx >> 5, c4 = idx & 31;
            float4 kk = *(const float4*)&Kp[(long)r * Lsp + l0 + c4 * 4];
            uint32_t h0, l0w, h1, l1w;
            packbf2(kk.x, kk.y, h0, l0w); packbf2(kk.z, kk.w, h1, l1w);
            *(uint4*)&Ks[r * STR2 + ((2 * c4) ^ ((r >> 1) & 2))] =
                make_uint4(h0, l0w, h1, l1w);
        }
        __syncthreads();
#pragma unroll
        for (int k0 = 0; k0 < 128; k0 += 16) {
            const int kx = (k0 / 2 + tig) ^ xf;
            uint32_t bh[4][2], bl[4][2];
#pragma unroll
            for (int nt = 0; nt < 4; nt++) {
                int n = n0b + nt * 8 + gid;
                uint2 P0 = Ks[n * STR2 + kx];
                uint2 P1 = Ks[n * STR2 + kx + 4];
                bh[nt][0] = P0.x; bl[nt][0] = P0.y;
                bh[nt][1] = P1.x; bl[nt][1] = P1.y;
            }
#pragma unroll
            for (int mt = 0; mt < 2; mt++) {
                int r0 = m0b + mt * 16 + gid, r1 = r0 + 8;
                uint2 Pa = Qs[r0 * STR2 + kx];
                uint2 Pb = Qs[r1 * STR2 + kx];
                uint2 Pc = Qs[r0 * STR2 + kx + 4];
                uint2 Pd = Qs[r1 * STR2 + kx + 4];
                uint32_t ah[4] = {Pa.x, Pb.x, Pc.x, Pd.x};
                uint32_t al[4] = {Pa.y, Pb.y, Pc.y, Pd.y};
#pragma unroll
                for (int nt = 0; nt < 4; nt++)
                    mma3bf(acc[mt * 4 + nt], ah, al,
                           bh[nt][0], bh[nt][1], bl[nt][0], bl[nt][1]);
            }
        }
    }
    float* ap = atp + (long)lp * (Bb * 65536) + (long)b * 65536 + (long)c0 * 512;
#pragma unroll
    for (int mt = 0; mt < 2; mt++)
#pragma unroll
        for (int nt = 0; nt < 4; nt++) {
            int m = m0b + mt * 16 + gid;
            int n = kt + n0b + nt * 8 + tig * 2;
            float* a = acc[mt * 4 + nt];
            *(float2*)&ap[(long)m * 512 + n] = make_float2(a[0], a[1]);
            *(float2*)&ap[(long)(m + 8) * 512 + n] = make_float2(a[2], a[3]);
        }
}

// ---------------------------------------------------------------------------
// masked softmax: sums 4 qk partials, scales by 1/64, writes probs
// ---------------------------------------------------------------------------
__global__ __launch_bounds__(128) void softmax_v6(
    const float* __restrict__ atp, float* __restrict__ at,
    const int* __restrict__ mask)
{
    __shared__ float sm[128];
    const int row = blockIdx.x;
    const int b = row >> 7;
    const int t = threadIdx.x;
    const float sc = 0.015625f;
    const long roff = (long)row * 512;
    const long pstr = (long)Bb * 65536;

    float v[4];
    float mx = -INFINITY;
#pragma unroll
    for (int j = 0; j < 4; j++) {
        bool on = mask[b * 4 + j] > 0;
        float sum = atp[roff + j * 128 + t] + atp[pstr + roff + j * 128 + t]
                  + atp[2 * pstr + roff + j * 128 + t] + atp[3 * pstr + roff + j * 128 + t];
        v[j] = on ? sum * sc : -INFINITY;
        mx = fmaxf(mx, v[j]);
    }
    sm[t] = mx; __syncthreads();
    for (int s = 64; s > 0; s >>= 1) {
        if (t < s) sm[t] = fmaxf(sm[t], sm[t + s]);
        __syncthreads();
    }
    mx = sm[0]; __syncthreads();

    float sum = 0.f;
#pragma unroll
    for (int j = 0; j < 4; j++) {
        v[j] = (v[j] == -INFINITY) ? 0.f : expf(v[j] - mx);
        sum += v[j];
    }
    sm[t] = sum; __syncthreads();
    for (int s = 64; s > 0; s >>= 1) {
        if (t < s) sm[t] += sm[t + s];
        __syncthreads();
    }
    float inv = 1.f / sm[0];
#pragma unroll
    for (int j = 0; j < 4; j++) at[roff + j * 128 + t] = v[j] * inv;
}

// ---------------------------------------------------------------------------
// av: x[b][c][lt+n] = sum_k attn[b][c][k] * V^T[b][lt+n][k]
// packed-bf16, tile m128c x n64l, k-chunks 64. grid (64, Bb)
// ---------------------------------------------------------------------------
#define ASTR 36
#define AV_A2 (128*ASTR)
#define AV_B2 (64*ASTR)
#define AV_SMEM ((AV_A2 + AV_B2)*8)   // 55296 B
__global__ __launch_bounds__(256, 2) void av_v9(
    const float* __restrict__ at, const float* __restrict__ vT,
    float* __restrict__ xout)
{
    extern __shared__ uint2 sm2[];
    uint2* Aa = sm2;               // attn [128][ASTR]
    uint2* Vs = sm2 + AV_A2;       // V^T  [64][ASTR]
    const int tid = threadIdx.x;
    const int lane = tid & 31, wid = tid >> 5;
    const int gid = lane >> 2, tig = lane & 3;
    const int lt = blockIdx.x * 64;
    const int b = blockIdx.y;
    const float* ap = at + (long)b * 65536;
    const float* vp = vT + (long)b * ((long)Lsp * 512);
    const int xf = (gid >> 1) & 2;

    const int m0b = (wid >> 1) * 32, n0b = (wid & 1) * 32;
    float acc[8][4];
#pragma unroll
    for (int i = 0; i < 8; i++)
#pragma unroll
        for (int j = 0; j < 4; j++) acc[i][j] = 0.f;

    for (int kg = 0; kg < 512; kg += 64) {
        __syncthreads();
#pragma unroll
        for (int j = 0; j < 8; j++) {       // attn: 128 rows x 16 f4
            int idx = tid + j * 256;
            int r = idx >> 4, c4 = idx & 15;
            float4 a = *(const float4*)&ap[(long)r * 512 + kg + c4 * 4];
            uint32_t h0, l0w, h1, l1w;
            packbf2(a.x, a.y, h0, l0w); packbf2(a.z, a.w, h1, l1w);
            *(uint4*)&Aa[r * ASTR + ((2 * c4) ^ ((r >> 1) & 2))] =
                make_uint4(h0, l0w, h1, l1w);
        }
#pragma unroll
        for (int j = 0; j < 4; j++) {       // V^T: 64 rows x 16 f4
            int idx = tid + j * 256;
            int r = idx >> 4, c4 = idx & 15;
            float4 vv = *(const float4*)&vp[(long)(lt + r) * 512 + kg + c4 * 4];
            uint32_t h0, l0w, h1, l1w;
            packbf2(vv.x, vv.y, h0, l0w); packbf2(vv.z, vv.w, h1, l1w);
            *(uint4*)&Vs[r * ASTR + ((2 * c4) ^ ((r >> 1) & 2))] =
                make_uint4(h0, l0w, h1, l1w);
        }
        __syncthreads();
#pragma unroll
        for (int k0 = 0; k0 < 64; k0 += 16) {
            const int kx = (k0 / 2 + tig) ^ xf;
            uint32_t bh[4][2], bl[4][2];
#pragma unroll
            for (int nt = 0; nt < 4; nt++) {
                int n = n0b + nt * 8 + gid;
                uint2 P0 = Vs[n * ASTR + kx];
                uint2 P1 = Vs[n * ASTR + kx + 4];
                bh[nt][0] = P0.x; bl[nt][0] = P0.y;
                bh[nt][1] = P1.x; bl[nt][1] = P1.y;
            }
#pragma unroll
            for (int mt = 0; mt < 2; mt++) {
                int r0 = m0b + mt * 16 + gid, r1 = r0 + 8;
                uint2 Pa = Aa[r0 * ASTR + kx];
                uint2 Pb = Aa[r1 * ASTR + kx];
                uint2 Pc = Aa[r0 * ASTR + kx + 4];
                uint2 Pd = Aa[r1 * ASTR + kx + 4];
                uint32_t ah[4] = {Pa.x, Pb.x, Pc.x, Pd.x};
                uint32_t al[4] = {Pa.y, Pb.y, Pc.y, Pd.y};
#pragma unroll
                for (int nt = 0; nt < 4; nt++)
                    mma3bf(acc[mt * 4 + nt], ah, al,
                           bh[nt][0], bh[nt][1], bl[nt][0], bl[nt][1]);
            }
        }
    }
    float* xp = xout + (long)b * CL + lt;
#pragma unroll
    for (int mt = 0; mt < 2; mt++)
#pragma unroll
        for (int nt = 0; nt < 4; nt++) {
            int m = m0b + mt * 16 + gid;
            int n = n0b + nt * 8 + tig * 2;
            float* a = acc[mt * 4 + nt];
            *(float2*)&xp[(long)m * Lsp + n] = make_float2(a[0], a[1]);
            *(float2*)&xp[(long)(m + 8) * Lsp + n] = make_float2(a[2], a[3]);
        }
}

// ---------------------------------------------------------------------------
// Depthwise 3x3x3 + bias, float4 loads
// ---------------------------------------------------------------------------
__global__ __launch_bounds__(256) void dw_v3(
    const float* __restrict__ inb, float* __restrict__ outb,
    long iz, long ib,
    const float* __restrict__ w27b, const float* __restrict__ biasb, int blk0)
{
    __shared__ float sp[16 * 324];
    const int tid = threadIdx.x;
    const int x = tid & 15, y = tid >> 4;
    const int c = blockIdx.x, b = blockIdx.y, z = blockIdx.z;
    const int blk = blk0 + z;

    const float* in = inb + (long)z * iz + (long)b * ib + (long)c * Lsp;
    float* out = outb + (long)z * iz + (long)b * ib + (long)c * Lsp;
    const float* wv = w27b + (long)blk * Cch * 27 + c * 27;
    const float bias = biasb[blk * Cch + c];

    for (int idx = tid; idx < 16 * 324; idx += 256) sp[idx] = 0.f;
    __syncthreads();
    const float4* in4 = (const float4*)in;
#pragma unroll
    for (int j = 0; j < 4; j++) {
        int i4 = tid + j * 256;
        float4 vv = in4[i4];
        int zz = i4 >> 6, rem = i4 & 63;
        float* dst = &sp[zz * 324 + ((rem >> 2) + 1) * 18 + (rem & 3) * 4 + 1];
        dst[0] = vv.x; dst[1] = vv.y; dst[2] = vv.z; dst[3] = vv.w;
    }
    float w[27];
#pragma unroll
    for (int k = 0; k < 27; k++) w[k] = wv[k];
    __syncthreads();

    float p0[9], p1[9], p2[9];
#pragma unroll
    for (int k = 0; k < 9; k++) p0[k] = 0.f;
#pragma unroll
    for (int dy = 0; dy < 3; dy++)
#pragma unroll
        for (int dx = 0; dx < 3; dx++)
            p1[dy * 3 + dx] = sp[(y + dy) * 18 + (x + dx)];

#pragma unroll
    for (int zz = 0; zz < 16; zz++) {
        if (zz < 15) {
#pragma unroll
            for (int dy = 0; dy < 3; dy++)
#pragma unroll
                for (int dx = 0; dx < 3; dx++)
                    p2[dy * 3 + dx] = sp[(zz + 1) * 324 + (y + dy) * 18 + (x + dx)];
        } else {
#pragma unroll
            for (int k = 0; k < 9; k++) p2[k] = 0.f;
        }
        float a = bias;
#pragma unroll
        for (int k = 0; k < 9; k++) a += p0[k] * w[k];
#pragma unroll
        for (int k = 0; k < 9; k++) a += p1[k] * w[9 + k];
#pragma unroll
        for (int k = 0; k < 9; k++) a += p2[k] * w[18 + k];
        out[zz * 256 + tid] = a;
#pragma unroll
        for (int k = 0; k < 9; k++) { p0[k] = p1[k]; p1[k] = p2[k]; }
    }
}

// ---------------------------------------------------------------------------
extern "C" void kernel_launch(void* const* d_in, const int* in_sizes, int n_in,
                              void* d_out, int out_size)
{
    const float* query = (const float*)d_in[0];
    const float* m0 = (const float*)d_in[1];
    const float* m1 = (const float*)d_in[2];
    const float* m2 = (const float*)d_in[3];
    const float* m3 = (const float*)d_in[4];
    const int*   mask  = (const int*)d_in[5];
    const float* pw1_w = (const float*)d_in[6];
    const float* pw1_b = (const float*)d_in[7];
    const float* ln1_g = (const float*)d_in[8];
    const float* ln1_b = (const float*)d_in[9];
    const float* dw_w  = (const float*)d_in[10];
    const float* dw_b  = (const float*)d_in[11];
    const float* ln2_g = (const float*)d_in[12];
    const float* ln2_b = (const float*)d_in[13];
    const float* pw2_w = (const float*)d_in[14];
    const float* pw2_b = (const float*)d_in[15];
    const float* ln3_g = (const float*)d_in[16];
    const float* ln3_b = (const float*)d_in[17];
    float* out = (float*)d_out;

    float *y1, *y2, *qb, *kv, *xb, *at, *atp;
    cudaGetSymbolAddress((void**)&y1, g_y1);
    cudaGetSymbolAddress((void**)&y2, g_y2);
    cudaGetSymbolAddress((void**)&qb, g_q);
    cudaGetSymbolAddress((void**)&kv, g_KV);
    cudaGetSymbolAddress((void**)&xb, g_x);
    cudaGetSymbolAddress((void**)&at, g_at);
    cudaGetSymbolAddress((void**)&atp, g_atp);
    float* Kb = kv;
    float* Vt = kv + (long)Bb * C4L;

    cudaFuncSetAttribute(pw_v10, cudaFuncAttributeMaxDynamicSharedMemorySize, PW_SMEM);
    cudaFuncSetAttribute(qk_v9, cudaFuncAttributeMaxDynamicSharedMemorySize, QK_SMEM);
    cudaFuncSetAttribute(av_v9, cudaFuncAttributeMaxDynamicSharedMemorySize, AV_SMEM);

    // ---- weight prepack (packed bf16 hi/lo, swizzled) ----
    prep_w<<<20, 256>>>(pw1_w, pw2_w);

    // ---- blocks 0..8 (query + K/V maps) ----
    pw_v10<<<dim3(64, Bb, 9), 256, PW_SMEM>>>(
        query, m0, m1, m2, m3, /*imode=*/1, /*wofs=*/0,
        pw1_b, ln1_g, ln1_b, ln1_g, ln1_b, /*blk0=*/0,
        nullptr, y1, nullptr, /*omode=*/1, /*flags=*/2);
    dw_v3<<<dim3(Cch, Bb, 9), 256>>>(y1, y2, BCL, CL, dw_w, dw_b, 0);
    pw_v10<<<dim3(64, Bb, 9), 256, PW_SMEM>>>(
        y2, nullptr, nullptr, nullptr, nullptr, /*imode=*/2, /*wofs=*/10,
        pw2_b, ln2_g, ln2_b, ln3_g, ln3_b, /*blk0=*/0,
        nullptr, qb, kv, /*omode=*/2, /*flags=*/1);

    // ---- attention ----
    qk_v9<<<dim3(4, 4, 16), 256, QK_SMEM>>>(qb, Kb, atp);
    softmax_v6<<<Bb * 128, 128>>>(atp, at, mask);
    av_v9<<<dim3(64, Bb), 256, AV_SMEM>>>(at, Vt, xb);

    // ---- out_project (blk 9) + residual ----
    pw_v10<<<dim3(64, Bb, 1), 256, PW_SMEM>>>(
        xb, nullptr, nullptr, nullptr, nullptr, /*imode=*/0, /*wofs=*/0,
        pw1_b, ln1_g, ln1_b, ln1_g, ln1_b, /*blk0=*/9,
        nullptr, y1, nullptr, /*omode=*/0, /*flags=*/2);
    dw_v3<<<dim3(Cch, Bb, 1), 256>>>(y1, y2, BCL, CL, dw_w, dw_b, 9);
    pw_v10<<<dim3(64, Bb, 1), 256, PW_SMEM>>>(
        y2, nullptr, nullptr, nullptr, nullptr, /*imode=*/0, /*wofs=*/10,
        pw2_b, ln2_g, ln2_b, ln3_g, ln3_b, /*blk0=*/9,
        query, out, nullptr, /*omode=*/0, /*flags=*/1 | 4);
}

// round 14
// speedup vs baseline: 1.2403x; 1.0533x over previous
#include <cuda_runtime.h>
#include <math.h>
#include <stdint.h>

#define Bb   8
#define Cch  128
#define Lsp  4096
#define CL   (Cch*Lsp)        // 524288
#define C4L  (4*CL)
#define BCL  (Bb*CL)

// ---------------- scratch (static device memory) ----------------------------
__device__ float g_y1[9*BCL];
__device__ float g_y2[9*BCL];
__device__ float g_q [BCL];
__device__ float g_KV[2*Bb*C4L];          // K: [B][4C][L] ; V^T: [B][L][4C]
__device__ float g_x [BCL];
__device__ float g_at [Bb*128*512];       // softmax probs
__device__ float g_atp[4*Bb*128*512];     // qk partials (4 L-parts)
__device__ uint32_t g_Wpk[20*2*128*68];   // prepacked W: per-matrix Wh plane | Wl plane

__device__ __forceinline__ float gelu_exact(float x) {
    return 0.5f * x * (1.0f + erff(x * 0.70710678118654752f));
}

// ======================= bf16 hi/lo split-pack ==============================
__device__ __forceinline__ void packbf2(float x0, float x1, uint32_t& h, uint32_t& l) {
    asm("cvt.rn.bf16x2.f32 %0, %1, %2;" : "=r"(h) : "f"(x1), "f"(x0));
    float h0 = __uint_as_float(h << 16);
    float h1 = __uint_as_float(h & 0xffff0000u);
    asm("cvt.rn.bf16x2.f32 %0, %1, %2;" : "=r"(l) : "f"(x1 - h1), "f"(x0 - h0));
}

__device__ __forceinline__ void mmabf(float* d,
    uint32_t a0, uint32_t a1, uint32_t a2, uint32_t a3, uint32_t b0, uint32_t b1)
{
    asm volatile(
        "mma.sync.aligned.m16n8k16.row.col.f32.bf16.bf16.f32 "
        "{%0,%1,%2,%3}, {%4,%5,%6,%7}, {%8,%9}, {%0,%1,%2,%3};"
        : "+f"(d[0]), "+f"(d[1]), "+f"(d[2]), "+f"(d[3])
        : "r"(a0), "r"(a1), "r"(a2), "r"(a3), "r"(b0), "r"(b1));
}
__device__ __forceinline__ void mma3bf(float* d,
    const uint32_t* ah, const uint32_t* al,
    uint32_t bh0, uint32_t bh1, uint32_t bl0, uint32_t bl1)
{
    mmabf(d, ah[0], ah[1], ah[2], ah[3], bl0, bl1);
    mmabf(d, al[0], al[1], al[2], al[3], bh0, bh1);
    mmabf(d, ah[0], ah[1], ah[2], ah[3], bh0, bh1);
}

// ---------------------------------------------------------------------------
// Weight prepack: [o][c] fp32 -> Wh plane [128][68] then Wl plane [128][68].
// Matches pw's smem layout exactly (Wh || Wl contiguous), so pw stages W with
// a flat uint4 copy, zero conversions.
// ---------------------------------------------------------------------------
__global__ __launch_bounds__(256) void prep_w(
    const float* __restrict__ w1, const float* __restrict__ w2)
{
    const int mi = blockIdx.x;
    const float* src = mi < 10 ? w1 + (long)mi * 16384 : w2 + (long)(mi - 10) * 16384;
    uint32_t* dh = g_Wpk + (long)mi * 17408;
    uint32_t* dl = dh + 8704;
    const int tid = threadIdx.x;
#pragma unroll
    for (int i = 0; i < 16; i++) {
        int idx = tid + i * 256;            // 4096 float4
        int o = idx >> 5, c4 = idx & 31;
        float4 w = *(const float4*)&src[o * 128 + c4 * 4];
        uint32_t h0, l0, h1, l1;
        packbf2(w.x, w.y, h0, l0);
        packbf2(w.z, w.w, h1, l1);
        *(uint2*)&dh[o * 68 + c4 * 2] = make_uint2(h0, h1);
        *(uint2*)&dl[o * 68 + c4 * 2] = make_uint2(l0, l1);
    }
    for (int i = tid; i < 512; i += 256) {  // zero pad cols 64..67
        int o = i >> 2, w = 64 + (i & 3);
        dh[o * 68 + w] = 0; dl[o * 68 + w] = 0;
    }
}

// ---------------------------------------------------------------------------
// Fused pointwise block: 64-token x 128-out tile, 256 threads, 2 CTAs/SM.
// (v8 mainloop — separate hi/lo planes, LDS.32 — + prepacked-W flat copy.)
// imode: 0 inq+b*CL | 1 (z==0?inq:mods[(z-1)&3])+b*CL | 2 inq+z*BCL+b*CL
// omode: 0 out0+b*CL | 1 out0+z*BCL+b*CL | 2 z==0->out0; z in 1..4 K; z>=5 V^T
// flags: bit0 in LN+GELU, bit1 out GELU, bit2 residual
// ---------------------------------------------------------------------------
#define NW 68
#define AW (64*NW)      // 4352 words per A array
#define WW (128*NW)     // 8704 words per W array
#define CS_STR 132
#define PW_SMEM ((2*AW + 2*WW + 512 + 384) * 4)   // 108032 B

__global__ __launch_bounds__(256, 2) void pw_v11(
    const float* __restrict__ inq,
    const float* __restrict__ mm0, const float* __restrict__ mm1,
    const float* __restrict__ mm2, const float* __restrict__ mm3,
    int imode, int wofs,
    const float* __restrict__ biasb,
    const float* __restrict__ g1b, const float* __restrict__ b1b,
    const float* __restrict__ g2b, const float* __restrict__ b2b,
    int blk0,
    const float* __restrict__ res,
    float* __restrict__ out0, float* __restrict__ out1, int omode,
    int flags)
{
    extern __shared__ uint32_t smu[];
    uint32_t* Ah = smu;                // [64][NW]
    uint32_t* Al = smu + AW;
    uint32_t* Wh = smu + 2 * AW;       // [128][NW]  (Wh || Wl contiguous)
    uint32_t* Wl = smu + 2 * AW + WW;
    float* red = (float*)(smu + 2 * AW + 2 * WW);   // [2][4][64]
    float* ps  = red + 512;                          // bias | go | bo
    float* Cs  = (float*)smu;                        // epilogue alias (A region)

    const int tid = threadIdx.x;
    const int lane = tid & 31, wid = tid >> 5;
    const int gid = lane >> 2, tig = lane & 3;
    const int t = tid & 63, p = tid >> 6;       // token, channel-quarter
    const int cb = p * 32;
    const int b = blockIdx.y, z = blockIdx.z;
    const int l0 = blockIdx.x * 64;
    const int blk = blk0 + z;

    const float* src;
    if (imode == 0) src = inq;
    else if (imode == 1) {
        if (z == 0) src = inq;
        else { int zs = (z - 1) & 3; src = zs == 0 ? mm0 : zs == 1 ? mm1 : zs == 2 ? mm2 : mm3; }
    } else src = inq + (long)z * BCL;
    const float* inp = src + (long)b * CL + l0;

    const float* bias = biasb + blk * 128;
    const float* gi = g1b + blk * 128, *bi = b1b + blk * 128;
    const float* go = g2b + blk * 128, *bo = b2b + blk * 128;

    // ---- A loads: 4 threads per token, 32 channels each ----
    float v[32];
    float s = 0.f, q = 0.f;
#pragma unroll
    for (int i = 0; i < 32; i++) {
        v[i] = inp[(long)(cb + i) * Lsp + t];
        s += v[i]; q += v[i] * v[i];
    }
    // ---- W staging: flat uint4 copy from prepacked global (zero CVTs) ----
    {
        const uint4* wsrc = (const uint4*)(g_Wpk + (long)(wofs + blk) * 17408);
        uint4* wdst = (uint4*)Wh;
#pragma unroll
        for (int i = 0; i < 17; i++)
            wdst[tid + i * 256] = wsrc[tid + i * 256];
    }
    if (tid < 128) { ps[tid] = bias[tid]; ps[128 + tid] = go[tid]; ps[256 + tid] = bo[tid]; }

    if (flags & 1) {
        red[p * 64 + t] = s; red[256 + p * 64 + t] = q;
        __syncthreads();
        float S = red[t] + red[64 + t] + red[128 + t] + red[192 + t];
        float Q = red[256 + t] + red[320 + t] + red[384 + t] + red[448 + t];
        float mean = S * (1.f / 128.f);
        float rstd = rsqrtf(Q * (1.f / 128.f) - mean * mean + 1e-6f);
#pragma unroll
        for (int i = 0; i < 16; i++) {
            float x0 = gelu_exact((v[2*i]   - mean) * rstd * gi[cb + 2*i]   + bi[cb + 2*i]);
            float x1 = gelu_exact((v[2*i+1] - mean) * rstd * gi[cb + 2*i+1] + bi[cb + 2*i+1]);
            uint32_t h, l;
            packbf2(x0, x1, h, l);
            Ah[t * NW + cb / 2 + i] = h;
            Al[t * NW + cb / 2 + i] = l;
        }
    } else {
#pragma unroll
        for (int i = 0; i < 16; i++) {
            uint32_t h, l;
            packbf2(v[2*i], v[2*i+1], h, l);
            Ah[t * NW + cb / 2 + i] = h;
            Al[t * NW + cb / 2 + i] = l;
        }
    }
    __syncthreads();

    // ---- mainloop: 8 warps (2m x 4n), warp tile m32 x n32 (v8 proven) ----
    const int m0b = (wid >> 2) * 32, n0b = (wid & 3) * 32;
    float acc[8][4];
#pragma unroll
    for (int i = 0; i < 8; i++)
#pragma unroll
        for (int j = 0; j < 4; j++) acc[i][j] = 0.f;

#pragma unroll
    for (int k0 = 0; k0 < 128; k0 += 16) {
        const int kw = k0 / 2 + tig;
        uint32_t bh[4][2], bl[4][2];
#pragma unroll
        for (int nt = 0; nt < 4; nt++) {
            int n = n0b + nt * 8 + gid;
            bh[nt][0] = Wh[n * NW + kw];     bh[nt][1] = Wh[n * NW + kw + 4];
            bl[nt][0] = Wl[n * NW + kw];     bl[nt][1] = Wl[n * NW + kw + 4];
        }
#pragma unroll
        for (int mt = 0; mt < 2; mt++) {
            int r0 = m0b + mt * 16 + gid, r1 = r0 + 8;
            uint32_t ah[4], al[4];
            ah[0] = Ah[r0 * NW + kw];     ah[1] = Ah[r1 * NW + kw];
            ah[2] = Ah[r0 * NW + kw + 4]; ah[3] = Ah[r1 * NW + kw + 4];
            al[0] = Al[r0 * NW + kw];     al[1] = Al[r1 * NW + kw];
            al[2] = Al[r0 * NW + kw + 4]; al[3] = Al[r1 * NW + kw + 4];
#pragma unroll
            for (int nt = 0; nt < 4; nt++)
                mma3bf(acc[mt * 4 + nt], ah, al,
                       bh[nt][0], bh[nt][1], bl[nt][0], bl[nt][1]);
        }
    }
    __syncthreads();

    // ---- C -> smem (alias A region: 64 x CS_STR <= 2*AW) ----
#pragma unroll
    for (int mt = 0; mt < 2; mt++)
#pragma unroll
        for (int nt = 0; nt < 4; nt++) {
            int m = m0b + mt * 16 + gid, n = n0b + nt * 8 + tig * 2;
            float* a = acc[mt * 4 + nt];
            *(float2*)&Cs[m * CS_STR + n] = make_float2(a[0], a[1]);
            *(float2*)&Cs[(m + 8) * CS_STR + n] = make_float2(a[2], a[3]);
        }
    __syncthreads();

    // ---- epilogue: +bias -> LN -> [GELU] -> [res] ----
    float w2[32];
    float s2 = 0.f, q2 = 0.f;
#pragma unroll
    for (int i = 0; i < 32; i++) {
        w2[i] = Cs[t * CS_STR + cb + i] + ps[cb + i];
        s2 += w2[i]; q2 += w2[i] * w2[i];
    }
    red[p * 64 + t] = s2; red[256 + p * 64 + t] = q2;
    __syncthreads();
    float S2 = red[t] + red[64 + t] + red[128 + t] + red[192 + t];
    float Q2 = red[256 + t] + red[320 + t] + red[384 + t] + red[448 + t];
    float mean2 = S2 * (1.f / 128.f);
    float rstd2 = rsqrtf(Q2 * (1.f / 128.f) - mean2 * mean2 + 1e-6f);
    const float* resp = (flags & 4) ? (res + (long)b * CL + l0) : nullptr;
    float buf[32];
#pragma unroll
    for (int i = 0; i < 32; i++) {
        int c = cb + i;
        float val = (w2[i] - mean2) * rstd2 * ps[128 + c] + ps[256 + c];
        if (flags & 2) val = gelu_exact(val);
        if (flags & 4) val += resp[(long)c * Lsp + t];
        buf[i] = val;
    }
    if (omode == 2 && z >= 5) {
        // V^T layout: [b][l][512], col offset (z-5)*128 + cb
        float* vp = out1 + (long)Bb * C4L + (long)b * ((long)Lsp * 512)
                  + (long)(l0 + t) * 512 + (z - 5) * 128 + cb;
#pragma unroll
        for (int j = 0; j < 8; j++)
            *(float4*)&vp[4 * j] = make_float4(buf[4*j], buf[4*j+1], buf[4*j+2], buf[4*j+3]);
    } else {
        float* outp;
        if (omode == 0) outp = out0 + (long)b * CL + l0;
        else if (omode == 1) outp = out0 + (long)z * BCL + (long)b * CL + l0;
        else if (z == 0) outp = out0 + (long)b * CL + l0;
        else outp = out1 + (long)(z - 1) * CL + (long)b * C4L + l0;   // K layout
#pragma unroll
        for (int i = 0; i < 32; i++)
            outp[(long)(cb + i) * Lsp + t] = buf[i];
    }
}

// ---------------------------------------------------------------------------
// qk partial: 64c x 128k tile, 256 threads, 2 CTAs/SM (v8 proven, verbatim).
// grid (4 kt, 4 lp, 16 = b*2+ct)
// ---------------------------------------------------------------------------
#define QK_SMEM ((2*AW + 2*WW) * 4)   // 104448 B
__global__ __launch_bounds__(256, 2) void qk_v8(
    const float* __restrict__ q, const float* __restrict__ K,
    float* __restrict__ atp)
{
    extern __shared__ uint32_t smu[];
    uint32_t* Qh = smu;                // [64][NW]
    uint32_t* Ql = smu + AW;
    uint32_t* Kh = smu + 2 * AW;       // [128][NW]
    uint32_t* Kl = smu + 2 * AW + WW;
    const int tid = threadIdx.x;
    const int lane = tid & 31, wid = tid >> 5;
    const int gid = lane >> 2, tig = lane & 3;
    const int kt = blockIdx.x * 128, lp = blockIdx.y;
    const int b = blockIdx.z >> 1, ct = blockIdx.z & 1;
    const int c0 = ct * 64;
    const float* qp = q + (long)b * CL + (long)c0 * Lsp;
    const float* Kp = K + (long)b * C4L + (long)kt * Lsp;
    const int lbase = lp * 1024;

    const int m0b = (wid >> 2) * 32, n0b = (wid & 3) * 32;
    float acc[8][4];
#pragma unroll
    for (int i = 0; i < 8; i++)
#pragma unroll
        for (int j = 0; j < 4; j++) acc[i][j] = 0.f;

    for (int lc = 0; lc < 1024; lc += 128) {
        const int l0 = lbase + lc;
        __syncthreads();
#pragma unroll
        for (int j = 0; j < 8; j++) {       // Q: 64 rows x 32 f4
            int idx = tid + j * 256;
            int r = idx >> 5, c4 = idx & 31;
            float4 a = *(const float4*)&qp[(long)r * Lsp + l0 + c4 * 4];
            uint32_t h0, l0w, h1, l1w;
            packbf2(a.x, a.y, h0, l0w); packbf2(a.z, a.w, h1, l1w);
            *(uint2*)&Qh[r * NW + c4 * 2] = make_uint2(h0, h1);
            *(uint2*)&Ql[r * NW + c4 * 2] = make_uint2(l0w, l1w);
        }
#pragma unroll
        for (int j = 0; j < 16; j++) {      // K: 128 rows x 32 f4
            int idx = tid + j * 256;
            int r = idx >> 5, c4 = idx & 31;
            float4 kk = *(const float4*)&Kp[(long)r * Lsp + l0 + c4 * 4];
            uint32_t h0, l0w, h1, l1w;
            packbf2(kk.x, kk.y, h0, l0w); packbf2(kk.z, kk.w, h1, l1w);
            *(uint2*)&Kh[r * NW + c4 * 2] = make_uint2(h0, h1);
            *(uint2*)&Kl[r * NW + c4 * 2] = make_uint2(l0w, l1w);
        }
        __syncthreads();
#pragma unroll
        for (int k0 = 0; k0 < 128; k0 += 16) {
            const int kw = k0 / 2 + tig;
            uint32_t bh[4][2], bl[4][2];
#pragma unroll
            for (int nt = 0; nt < 4; nt++) {
                int n = n0b + nt * 8 + gid;
                bh[nt][0] = Kh[n * NW + kw];     bh[nt][1] = Kh[n * NW + kw + 4];
                bl[nt][0] = Kl[n * NW + kw];     bl[nt][1] = Kl[n * NW + kw + 4];
            }
#pragma unroll
            for (int mt = 0; mt < 2; mt++) {
                int r0 = m0b + mt * 16 + gid, r1 = r0 + 8;
                uint32_t ah[4], al[4];
                ah[0] = Qh[r0 * NW + kw];     ah[1] = Qh[r1 * NW + kw];
                ah[2] = Qh[r0 * NW + kw + 4]; ah[3] = Qh[r1 * NW + kw + 4];
                al[0] = Ql[r0 * NW + kw];     al[1] = Ql[r1 * NW + kw];
                al[2] = Ql[r0 * NW + kw + 4]; al[3] = Ql[r1 * NW + kw + 4];
#pragma unroll
                for (int nt = 0; nt < 4; nt++)
                    mma3bf(acc[mt * 4 + nt], ah, al,
                           bh[nt][0], bh[nt][1], bl[nt][0], bl[nt][1]);
            }
        }
    }
    float* ap = atp + (long)lp * (Bb * 65536) + (long)b * 65536 + (long)c0 * 512;
#pragma unroll
    for (int mt = 0; mt < 2; mt++)
#pragma unroll
        for (int nt = 0; nt < 4; nt++) {
            int m = m0b + mt * 16 + gid;
            int n = kt + n0b + nt * 8 + tig * 2;
            float* a = acc[mt * 4 + nt];
            *(float2*)&ap[(long)m * 512 + n] = make_float2(a[0], a[1]);
            *(float2*)&ap[(long)(m + 8) * 512 + n] = make_float2(a[2], a[3]);
        }
}

// ---------------------------------------------------------------------------
// masked softmax: sums 4 qk partials, scales by 1/64, writes probs
// ---------------------------------------------------------------------------
__global__ __launch_bounds__(128) void softmax_v6(
    const float* __restrict__ atp, float* __restrict__ at,
    const int* __restrict__ mask)
{
    __shared__ float sm[128];
    const int row = blockIdx.x;
    const int b = row >> 7;
    const int t = threadIdx.x;
    const float sc = 0.015625f;
    const long roff = (long)row * 512;
    const long pstr = (long)Bb * 65536;

    float v[4];
    float mx = -INFINITY;
#pragma unroll
    for (int j = 0; j < 4; j++) {
        bool on = mask[b * 4 + j] > 0;
        float sum = atp[roff + j * 128 + t] + atp[pstr + roff + j * 128 + t]
                  + atp[2 * pstr + roff + j * 128 + t] + atp[3 * pstr + roff + j * 128 + t];
        v[j] = on ? sum * sc : -INFINITY;
        mx = fmaxf(mx, v[j]);
    }
    sm[t] = mx; __syncthreads();
    for (int s = 64; s > 0; s >>= 1) {
        if (t < s) sm[t] = fmaxf(sm[t], sm[t + s]);
        __syncthreads();
    }
    mx = sm[0]; __syncthreads();

    float sum = 0.f;
#pragma unroll
    for (int j = 0; j < 4; j++) {
        v[j] = (v[j] == -INFINITY) ? 0.f : expf(v[j] - mx);
        sum += v[j];
    }
    sm[t] = sum; __syncthreads();
    for (int s = 64; s > 0; s >>= 1) {
        if (t < s) sm[t] += sm[t + s];
        __syncthreads();
    }
    float inv = 1.f / sm[0];
#pragma unroll
    for (int j = 0; j < 4; j++) at[roff + j * 128 + t] = v[j] * inv;
}

// ---------------------------------------------------------------------------
// av: x[b][c][lt+n] = sum_k attn[b][c][k] * V^T[b][lt+n][k]
// packed-bf16, tile m128c x n64l, k-chunks 64. grid (64, Bb)  (R13 proven)
// ---------------------------------------------------------------------------
#define ASTR 36
#define AV_A2 (128*ASTR)
#define AV_B2 (64*ASTR)
#define AV_SMEM ((AV_A2 + AV_B2)*8)   // 55296 B
__global__ __launch_bounds__(256, 2) void av_v9(
    const float* __restrict__ at, const float* __restrict__ vT,
    float* __restrict__ xout)
{
    extern __shared__ uint2 sm2[];
    uint2* Aa = sm2;               // attn [128][ASTR]
    uint2* Vs = sm2 + AV_A2;       // V^T  [64][ASTR]
    const int tid = threadIdx.x;
    const int lane = tid & 31, wid = tid >> 5;
    const int gid = lane >> 2, tig = lane & 3;
    const int lt = blockIdx.x * 64;
    const int b = blockIdx.y;
    const float* ap = at + (long)b * 65536;
    const float* vp = vT + (long)b * ((long)Lsp * 512);
    const int xf = (gid >> 1) & 2;

    const int m0b = (wid >> 1) * 32, n0b = (wid & 1) * 32;
    float acc[8][4];
#pragma unroll
    for (int i = 0; i < 8; i++)
#pragma unroll
        for (int j = 0; j < 4; j++) acc[i][j] = 0.f;

    for (int kg = 0; kg < 512; kg += 64) {
        __syncthreads();
#pragma unroll
        for (int j = 0; j < 8; j++) {       // attn: 128 rows x 16 f4
            int idx = tid + j * 256;
            int r = idx >> 4, c4 = idx & 15;
            float4 a = *(const float4*)&ap[(long)r * 512 + kg + c4 * 4];
            uint32_t h0, l0w, h1, l1w;
            packbf2(a.x, a.y, h0, l0w); packbf2(a.z, a.w, h1, l1w);
            *(uint4*)&Aa[r * ASTR + ((2 * c4) ^ ((r >> 1) & 2))] =
                make_uint4(h0, l0w, h1, l1w);
        }
#pragma unroll
        for (int j = 0; j < 4; j++) {       // V^T: 64 rows x 16 f4
            int idx = tid + j * 256;
            int r = idx >> 4, c4 = idx & 15;
            float4 vv = *(const float4*)&vp[(long)(lt + r) * 512 + kg + c4 * 4];
            uint32_t h0, l0w, h1, l1w;
            packbf2(vv.x, vv.y, h0, l0w); packbf2(vv.z, vv.w, h1, l1w);
            *(uint4*)&Vs[r * ASTR + ((2 * c4) ^ ((r >> 1) & 2))] =
                make_uint4(h0, l0w, h1, l1w);
        }
        __syncthreads();
#pragma unroll
        for (int k0 = 0; k0 < 64; k0 += 16) {
            const int kx = (k0 / 2 + tig) ^ xf;
            uint32_t bh[4][2], bl[4][2];
#pragma unroll
            for (int nt = 0; nt < 4; nt++) {
                int n = n0b + nt * 8 + gid;
                uint2 P0 = Vs[n * ASTR + kx];
                uint2 P1 = Vs[n * ASTR + kx + 4];
                bh[nt][0] = P0.x; bl[nt][0] = P0.y;
                bh[nt][1] = P1.x; bl[nt][1] = P1.y;
            }
#pragma unroll
            for (int mt = 0; mt < 2; mt++) {
                int r0 = m0b + mt * 16 + gid, r1 = r0 + 8;
                uint2 Pa = Aa[r0 * ASTR + kx];
                uint2 Pb = Aa[r1 * ASTR + kx];
                uint2 Pc = Aa[r0 * ASTR + kx + 4];
                uint2 Pd = Aa[r1 * ASTR + kx + 4];
                uint32_t ah[4] = {Pa.x, Pb.x, Pc.x, Pd.x};
                uint32_t al[4] = {Pa.y, Pb.y, Pc.y, Pd.y};
#pragma unroll
                for (int nt = 0; nt < 4; nt++)
                    mma3bf(acc[mt * 4 + nt], ah, al,
                           bh[nt][0], bh[nt][1], bl[nt][0], bl[nt][1]);
            }
        }
    }
    float* xp = xout + (long)b * CL + lt;
#pragma unroll
    for (int mt = 0; mt < 2; mt++)
#pragma unroll
        for (int nt = 0; nt < 4; nt++) {
            int m = m0b + mt * 16 + gid;
            int n = n0b + nt * 8 + tig * 2;
            float* a = acc[mt * 4 + nt];
            *(float2*)&xp[(long)m * Lsp + n] = make_float2(a[0], a[1]);
            *(float2*)&xp[(long)(m + 8) * Lsp + n] = make_float2(a[2], a[3]);
        }
}

// ---------------------------------------------------------------------------
// Depthwise 3x3x3 + bias, float4 loads
// ---------------------------------------------------------------------------
__global__ __launch_bounds__(256) void dw_v3(
    const float* __restrict__ inb, float* __restrict__ outb,
    long iz, long ib,
    const float* __restrict__ w27b, const float* __restrict__ biasb, int blk0)
{
    __shared__ float sp[16 * 324];
    const int tid = threadIdx.x;
    const int x = tid & 15, y = tid >> 4;
    const int c = blockIdx.x, b = blockIdx.y, z = blockIdx.z;
    const int blk = blk0 + z;

    const float* in = inb + (long)z * iz + (long)b * ib + (long)c * Lsp;
    float* out = outb + (long)z * iz + (long)b * ib + (long)c * Lsp;
    const float* wv = w27b + (long)blk * Cch * 27 + c * 27;
    const float bias = biasb[blk * Cch + c];

    for (int idx = tid; idx < 16 * 324; idx += 256) sp[idx] = 0.f;
    __syncthreads();
    const float4* in4 = (const float4*)in;
#pragma unroll
    for (int j = 0; j < 4; j++) {
        int i4 = tid + j * 256;
        float4 vv = in4[i4];
        int zz = i4 >> 6, rem = i4 & 63;
        float* dst = &sp[zz * 324 + ((rem >> 2) + 1) * 18 + (rem & 3) * 4 + 1];
        dst[0] = vv.x; dst[1] = vv.y; dst[2] = vv.z; dst[3] = vv.w;
    }
    float w[27];
#pragma unroll
    for (int k = 0; k < 27; k++) w[k] = wv[k];
    __syncthreads();

    float p0[9], p1[9], p2[9];
#pragma unroll
    for (int k = 0; k < 9; k++) p0[k] = 0.f;
#pragma unroll
    for (int dy = 0; dy < 3; dy++)
#pragma unroll
        for (int dx = 0; dx < 3; dx++)
            p1[dy * 3 + dx] = sp[(y + dy) * 18 + (x + dx)];

#pragma unroll
    for (int zz = 0; zz < 16; zz++) {
        if (zz < 15) {
#pragma unroll
            for (int dy = 0; dy < 3; dy++)
#pragma unroll
                for (int dx = 0; dx < 3; dx++)
                    p2[dy * 3 + dx] = sp[(zz + 1) * 324 + (y + dy) * 18 + (x + dx)];
        } else {
#pragma unroll
            for (int k = 0; k < 9; k++) p2[k] = 0.f;
        }
        float a = bias;
#pragma unroll
        for (int k = 0; k < 9; k++) a += p0[k] * w[k];
#pragma unroll
        for (int k = 0; k < 9; k++) a += p1[k] * w[9 + k];
#pragma unroll
        for (int k = 0; k < 9; k++) a += p2[k] * w[18 + k];
        out[zz * 256 + tid] = a;
#pragma unroll
        for (int k = 0; k < 9; k++) { p0[k] = p1[k]; p1[k] = p2[k]; }
    }
}

// ---------------------------------------------------------------------------
extern "C" void kernel_launch(void* const* d_in, const int* in_sizes, int n_in,
                              void* d_out, int out_size)
{
    const float* query = (const float*)d_in[0];
    const float* m0 = (const float*)d_in[1];
    const float* m1 = (const float*)d_in[2];
    const float* m2 = (const float*)d_in[3];
    const float* m3 = (const float*)d_in[4];
    const int*   mask  = (const int*)d_in[5];
    const float* pw1_w = (const float*)d_in[6];
    const float* pw1_b = (const float*)d_in[7];
    const float* ln1_g = (const float*)d_in[8];
    const float* ln1_b = (const float*)d_in[9];
    const float* dw_w  = (const float*)d_in[10];
    const float* dw_b  = (const float*)d_in[11];
    const float* ln2_g = (const float*)d_in[12];
    const float* ln2_b = (const float*)d_in[13];
    const float* pw2_w = (const float*)d_in[14];
    const float* pw2_b = (const float*)d_in[15];
    const float* ln3_g = (const float*)d_in[16];
    const float* ln3_b = (const float*)d_in[17];
    float* out = (float*)d_out;

    float *y1, *y2, *qb, *kv, *xb, *at, *atp;
    cudaGetSymbolAddress((void**)&y1, g_y1);
    cudaGetSymbolAddress((void**)&y2, g_y2);
    cudaGetSymbolAddress((void**)&qb, g_q);
    cudaGetSymbolAddress((void**)&kv, g_KV);
    cudaGetSymbolAddress((void**)&xb, g_x);
    cudaGetSymbolAddress((void**)&at, g_at);
    cudaGetSymbolAddress((void**)&atp, g_atp);
    float* Kb = kv;
    float* Vt = kv + (long)Bb * C4L;

    cudaFuncSetAttribute(pw_v11, cudaFuncAttributeMaxDynamicSharedMemorySize, PW_SMEM);
    cudaFuncSetAttribute(qk_v8, cudaFuncAttributeMaxDynamicSharedMemorySize, QK_SMEM);
    cudaFuncSetAttribute(av_v9, cudaFuncAttributeMaxDynamicSharedMemorySize, AV_SMEM);

    // ---- weight prepack (separate hi/lo planes matching pw smem layout) ----
    prep_w<<<20, 256>>>(pw1_w, pw2_w);

    // ---- blocks 0..8 (query + K/V maps) ----
    pw_v11<<<dim3(64, Bb, 9), 256, PW_SMEM>>>(
        query, m0, m1, m2, m3, /*imode=*/1, /*wofs=*/0,
        pw1_b, ln1_g, ln1_b, ln1_g, ln1_b, /*blk0=*/0,
        nullptr, y1, nullptr, /*omode=*/1, /*flags=*/2);
    dw_v3<<<dim3(Cch, Bb, 9), 256>>>(y1, y2, BCL, CL, dw_w, dw_b, 0);
    pw_v11<<<dim3(64, Bb, 9), 256, PW_SMEM>>>(
        y2, nullptr, nullptr, nullptr, nullptr, /*imode=*/2, /*wofs=*/10,
        pw2_b, ln2_g, ln2_b, ln3_g, ln3_b, /*blk0=*/0,
        nullptr, qb, kv, /*omode=*/2, /*flags=*/1);

    // ---- attention ----
    qk_v8<<<dim3(4, 4, 16), 256, QK_SMEM>>>(qb, Kb, atp);
    softmax_v6<<<Bb * 128, 128>>>(atp, at, mask);
    av_v9<<<dim3(64, Bb), 256, AV_SMEM>>>(at, Vt, xb);

    // ---- out_project (blk 9) + residual ----
    pw_v11<<<dim3(64, Bb, 1), 256, PW_SMEM>>>(
        xb, nullptr, nullptr, nullptr, nullptr, /*imode=*/0, /*wofs=*/0,
        pw1_b, ln1_g, ln1_b, ln1_g, ln1_b, /*blk0=*/9,
        nullptr, y1, nullptr, /*omode=*/0, /*flags=*/2);
    dw_v3<<<dim3(Cch, Bb, 1), 256>>>(y1, y2, BCL, CL, dw_w, dw_b, 9);
    pw_v11<<<dim3(64, Bb, 1), 256, PW_SMEM>>>(
        y2, nullptr, nullptr, nullptr, nullptr, /*imode=*/0, /*wofs=*/10,
        pw2_b, ln2_g, ln2_b, ln3_g, ln3_b, /*blk0=*/9,
        query, out, nullptr, /*omode=*/0, /*flags=*/1 | 4);
}

// round 15
// speedup vs baseline: 1.2799x; 1.0319x over previous
#include <cuda_runtime.h>
#include <math.h>
#include <stdint.h>

#define Bb   8
#define Cch  128
#define Lsp  4096
#define CL   (Cch*Lsp)        // 524288
#define C4L  (4*CL)
#define BCL  (Bb*CL)

// ---------------- scratch (static device memory) ----------------------------
__device__ float g_y1[9*BCL];
__device__ float g_y2[9*BCL];
__device__ float g_q [BCL];
__device__ float g_KV[2*Bb*C4L];          // K: [B][4C][L] ; V^T: [B][L][4C]
__device__ float g_x [BCL];
__device__ float g_at [Bb*128*512];       // softmax probs
__device__ float g_atp[4*Bb*128*512];     // qk partials (4 L-parts)
__device__ uint32_t g_Wpk[20*2*128*68];   // prepacked W: per-matrix Wh plane | Wl plane

__device__ __forceinline__ float gelu_exact(float x) {
    return 0.5f * x * (1.0f + erff(x * 0.70710678118654752f));
}

// ---- cp.async helpers (baseline PTX, sm_80+) --------------------------------
#define CP_ASYNC16(dst_u32, src_ptr) \
    asm volatile("cp.async.cg.shared.global [%0], [%1], 16;" \
                 :: "r"(dst_u32), "l"(src_ptr) : "memory")
#define CP_COMMIT() asm volatile("cp.async.commit_group;" ::: "memory")
#define CP_WAIT0()  asm volatile("cp.async.wait_group 0;" ::: "memory")

// ======================= bf16 hi/lo split-pack ==============================
__device__ __forceinline__ void packbf2(float x0, float x1, uint32_t& h, uint32_t& l) {
    asm("cvt.rn.bf16x2.f32 %0, %1, %2;" : "=r"(h) : "f"(x1), "f"(x0));
    float h0 = __uint_as_float(h << 16);
    float h1 = __uint_as_float(h & 0xffff0000u);
    asm("cvt.rn.bf16x2.f32 %0, %1, %2;" : "=r"(l) : "f"(x1 - h1), "f"(x0 - h0));
}

__device__ __forceinline__ void mmabf(float* d,
    uint32_t a0, uint32_t a1, uint32_t a2, uint32_t a3, uint32_t b0, uint32_t b1)
{
    asm volatile(
        "mma.sync.aligned.m16n8k16.row.col.f32.bf16.bf16.f32 "
        "{%0,%1,%2,%3}, {%4,%5,%6,%7}, {%8,%9}, {%0,%1,%2,%3};"
        : "+f"(d[0]), "+f"(d[1]), "+f"(d[2]), "+f"(d[3])
        : "r"(a0), "r"(a1), "r"(a2), "r"(a3), "r"(b0), "r"(b1));
}
__device__ __forceinline__ void mma3bf(float* d,
    const uint32_t* ah, const uint32_t* al,
    uint32_t bh0, uint32_t bh1, uint32_t bl0, uint32_t bl1)
{
    mmabf(d, ah[0], ah[1], ah[2], ah[3], bl0, bl1);
    mmabf(d, al[0], al[1], al[2], al[3], bh0, bh1);
    mmabf(d, ah[0], ah[1], ah[2], ah[3], bh0, bh1);
}

// ---------------------------------------------------------------------------
// Weight prepack: [o][c] fp32 -> Wh plane [128][68] then Wl plane [128][68].
// ---------------------------------------------------------------------------
__global__ __launch_bounds__(256) void prep_w(
    const float* __restrict__ w1, const float* __restrict__ w2)
{
    const int mi = blockIdx.x;
    const float* src = mi < 10 ? w1 + (long)mi * 16384 : w2 + (long)(mi - 10) * 16384;
    uint32_t* dh = g_Wpk + (long)mi * 17408;
    uint32_t* dl = dh + 8704;
    const int tid = threadIdx.x;
#pragma unroll
    for (int i = 0; i < 16; i++) {
        int idx = tid + i * 256;            // 4096 float4
        int o = idx >> 5, c4 = idx & 31;
        float4 w = *(const float4*)&src[o * 128 + c4 * 4];
        uint32_t h0, l0, h1, l1;
        packbf2(w.x, w.y, h0, l0);
        packbf2(w.z, w.w, h1, l1);
        *(uint2*)&dh[o * 68 + c4 * 2] = make_uint2(h0, h1);
        *(uint2*)&dl[o * 68 + c4 * 2] = make_uint2(l0, l1);
    }
    for (int i = tid; i < 512; i += 256) {  // zero pad cols 64..67
        int o = i >> 2, w = 64 + (i & 3);
        dh[o * 68 + w] = 0; dl[o * 68 + w] = 0;
    }
}

// ---------------------------------------------------------------------------
// Fused pointwise block: 64-token x 128-out tile, 256 threads, 2 CTAs/SM.
// v8 mainloop (separate hi/lo planes, LDS.32) + prepacked-W cp.async copy
// + smem-cached LN params.
// imode: 0 inq+b*CL | 1 (z==0?inq:mods[(z-1)&3])+b*CL | 2 inq+z*BCL+b*CL
// omode: 0 out0+b*CL | 1 out0+z*BCL+b*CL | 2 z==0->out0; z in 1..4 K; z>=5 V^T
// flags: bit0 in LN+GELU, bit1 out GELU, bit2 residual
// ---------------------------------------------------------------------------
#define NW 68
#define AW (64*NW)      // 4352 words per A array
#define WW (128*NW)     // 8704 words per W array
#define CS_STR 132
#define PW_SMEM ((2*AW + 2*WW + 512 + 640) * 4)   // 109056 B

__global__ __launch_bounds__(256, 2) void pw_v12(
    const float* __restrict__ inq,
    const float* __restrict__ mm0, const float* __restrict__ mm1,
    const float* __restrict__ mm2, const float* __restrict__ mm3,
    int imode, int wofs,
    const float* __restrict__ biasb,
    const float* __restrict__ g1b, const float* __restrict__ b1b,
    const float* __restrict__ g2b, const float* __restrict__ b2b,
    int blk0,
    const float* __restrict__ res,
    float* __restrict__ out0, float* __restrict__ out1, int omode,
    int flags)
{
    extern __shared__ uint32_t smu[];
    uint32_t* Ah = smu;                // [64][NW]
    uint32_t* Al = smu + AW;
    uint32_t* Wh = smu + 2 * AW;       // [128][NW]  (Wh || Wl contiguous)
    uint32_t* Wl = smu + 2 * AW + WW;
    float* red = (float*)(smu + 2 * AW + 2 * WW);   // [2][4][64]
    float* ps  = red + 512;            // bias | go | bo | gi | bi
    float* Cs  = (float*)smu;          // epilogue alias (A region)

    const int tid = threadIdx.x;
    const int lane = tid & 31, wid = tid >> 5;
    const int gid = lane >> 2, tig = lane & 3;
    const int t = tid & 63, p = tid >> 6;       // token, channel-quarter
    const int cb = p * 32;
    const int b = blockIdx.y, z = blockIdx.z;
    const int l0 = blockIdx.x * 64;
    const int blk = blk0 + z;

    const float* src;
    if (imode == 0) src = inq;
    else if (imode == 1) {
        if (z == 0) src = inq;
        else { int zs = (z - 1) & 3; src = zs == 0 ? mm0 : zs == 1 ? mm1 : zs == 2 ? mm2 : mm3; }
    } else src = inq + (long)z * BCL;
    const float* inp = src + (long)b * CL + l0;

    const float* bias = biasb + blk * 128;
    const float* gi = g1b + blk * 128, *bi = b1b + blk * 128;
    const float* go = g2b + blk * 128, *bo = b2b + blk * 128;

    // ---- W staging: cp.async flat copy from prepacked global (async) ----
    {
        const char* wsrc = (const char*)(g_Wpk + (long)(wofs + blk) * 17408) + tid * 16;
        uint32_t wdst = (uint32_t)__cvta_generic_to_shared((const char*)Wh + tid * 16);
#pragma unroll
        for (int i = 0; i < 17; i++)
            CP_ASYNC16(wdst + i * 4096, wsrc + (long)i * 4096);
        CP_COMMIT();
    }
    if (tid < 128) {
        ps[tid] = bias[tid]; ps[128 + tid] = go[tid]; ps[256 + tid] = bo[tid];
        ps[384 + tid] = gi[tid]; ps[512 + tid] = bi[tid];
    }

    // ---- A loads: 4 threads per token, 32 channels each ----
    float v[32];
    float s = 0.f, q = 0.f;
#pragma unroll
    for (int i = 0; i < 32; i++) {
        v[i] = inp[(long)(cb + i) * Lsp + t];
        s += v[i]; q += v[i] * v[i];
    }

    if (flags & 1) {
        red[p * 64 + t] = s; red[256 + p * 64 + t] = q;
        __syncthreads();
        float S = red[t] + red[64 + t] + red[128 + t] + red[192 + t];
        float Q = red[256 + t] + red[320 + t] + red[384 + t] + red[448 + t];
        float mean = S * (1.f / 128.f);
        float rstd = rsqrtf(Q * (1.f / 128.f) - mean * mean + 1e-6f);
#pragma unroll
        for (int i = 0; i < 16; i++) {
            float x0 = gelu_exact((v[2*i]   - mean) * rstd * ps[384 + cb + 2*i]   + ps[512 + cb + 2*i]);
            float x1 = gelu_exact((v[2*i+1] - mean) * rstd * ps[384 + cb + 2*i+1] + ps[512 + cb + 2*i+1]);
            uint32_t h, l;
            packbf2(x0, x1, h, l);
            Ah[t * NW + cb / 2 + i] = h;
            Al[t * NW + cb / 2 + i] = l;
        }
    } else {
#pragma unroll
        for (int i = 0; i < 16; i++) {
            uint32_t h, l;
            packbf2(v[2*i], v[2*i+1], h, l);
            Ah[t * NW + cb / 2 + i] = h;
            Al[t * NW + cb / 2 + i] = l;
        }
    }
    CP_WAIT0();
    __syncthreads();

    // ---- mainloop: 8 warps (2m x 4n), warp tile m32 x n32 (v8 proven) ----
    const int m0b = (wid >> 2) * 32, n0b = (wid & 3) * 32;
    float acc[8][4];
#pragma unroll
    for (int i = 0; i < 8; i++)
#pragma unroll
        for (int j = 0; j < 4; j++) acc[i][j] = 0.f;

#pragma unroll
    for (int k0 = 0; k0 < 128; k0 += 16) {
        const int kw = k0 / 2 + tig;
        uint32_t bh[4][2], bl[4][2];
#pragma unroll
        for (int nt = 0; nt < 4; nt++) {
            int n = n0b + nt * 8 + gid;
            bh[nt][0] = Wh[n * NW + kw];     bh[nt][1] = Wh[n * NW + kw + 4];
            bl[nt][0] = Wl[n * NW + kw];     bl[nt][1] = Wl[n * NW + kw + 4];
        }
#pragma unroll
        for (int mt = 0; mt < 2; mt++) {
            int r0 = m0b + mt * 16 + gid, r1 = r0 + 8;
            uint32_t ah[4], al[4];
            ah[0] = Ah[r0 * NW + kw];     ah[1] = Ah[r1 * NW + kw];
            ah[2] = Ah[r0 * NW + kw + 4]; ah[3] = Ah[r1 * NW + kw + 4];
            al[0] = Al[r0 * NW + kw];     al[1] = Al[r1 * NW + kw];
            al[2] = Al[r0 * NW + kw + 4]; al[3] = Al[r1 * NW + kw + 4];
#pragma unroll
            for (int nt = 0; nt < 4; nt++)
                mma3bf(acc[mt * 4 + nt], ah, al,
                       bh[nt][0], bh[nt][1], bl[nt][0], bl[nt][1]);
        }
    }
    __syncthreads();

    // ---- C -> smem (alias A region: 64 x CS_STR <= 2*AW) ----
#pragma unroll
    for (int mt = 0; mt < 2; mt++)
#pragma unroll
        for (int nt = 0; nt < 4; nt++) {
            int m = m0b + mt * 16 + gid, n = n0b + nt * 8 + tig * 2;
            float* a = acc[mt * 4 + nt];
            *(float2*)&Cs[m * CS_STR + n] = make_float2(a[0], a[1]);
            *(float2*)&Cs[(m + 8) * CS_STR + n] = make_float2(a[2], a[3]);
        }
    __syncthreads();

    // ---- epilogue: +bias -> LN -> [GELU] -> [res] ----
    float w2[32];
    float s2 = 0.f, q2 = 0.f;
#pragma unroll
    for (int i = 0; i < 32; i++) {
        w2[i] = Cs[t * CS_STR + cb + i] + ps[cb + i];
        s2 += w2[i]; q2 += w2[i] * w2[i];
    }
    red[p * 64 + t] = s2; red[256 + p * 64 + t] = q2;
    __syncthreads();
    float S2 = red[t] + red[64 + t] + red[128 + t] + red[192 + t];
    float Q2 = red[256 + t] + red[320 + t] + red[384 + t] + red[448 + t];
    float mean2 = S2 * (1.f / 128.f);
    float rstd2 = rsqrtf(Q2 * (1.f / 128.f) - mean2 * mean2 + 1e-6f);
    const float* resp = (flags & 4) ? (res + (long)b * CL + l0) : nullptr;
    float buf[32];
#pragma unroll
    for (int i = 0; i < 32; i++) {
        int c = cb + i;
        float val = (w2[i] - mean2) * rstd2 * ps[128 + c] + ps[256 + c];
        if (flags & 2) val = gelu_exact(val);
        if (flags & 4) val += resp[(long)c * Lsp + t];
        buf[i] = val;
    }
    if (omode == 2 && z >= 5) {
        // V^T layout: [b][l][512], col offset (z-5)*128 + cb
        float* vp = out1 + (long)Bb * C4L + (long)b * ((long)Lsp * 512)
                  + (long)(l0 + t) * 512 + (z - 5) * 128 + cb;
#pragma unroll
        for (int j = 0; j < 8; j++)
            *(float4*)&vp[4 * j] = make_float4(buf[4*j], buf[4*j+1], buf[4*j+2], buf[4*j+3]);
    } else {
        float* outp;
        if (omode == 0) outp = out0 + (long)b * CL + l0;
        else if (omode == 1) outp = out0 + (long)z * BCL + (long)b * CL + l0;
        else if (z == 0) outp = out0 + (long)b * CL + l0;
        else outp = out1 + (long)(z - 1) * CL + (long)b * C4L + l0;   // K layout
#pragma unroll
        for (int i = 0; i < 32; i++)
            outp[(long)(cb + i) * Lsp + t] = buf[i];
    }
}

// ---------------------------------------------------------------------------
// qk partial: 64c x 128k tile, 256 threads, 2 CTAs/SM (v8 proven, verbatim).
// grid (4 kt, 4 lp, 16 = b*2+ct)
// ---------------------------------------------------------------------------
#define QK_SMEM ((2*AW + 2*WW) * 4)   // 104448 B
__global__ __launch_bounds__(256, 2) void qk_v8(
    const float* __restrict__ q, const float* __restrict__ K,
    float* __restrict__ atp)
{
    extern __shared__ uint32_t smu[];
    uint32_t* Qh = smu;                // [64][NW]
    uint32_t* Ql = smu + AW;
    uint32_t* Kh = smu + 2 * AW;       // [128][NW]
    uint32_t* Kl = smu + 2 * AW + WW;
    const int tid = threadIdx.x;
    const int lane = tid & 31, wid = tid >> 5;
    const int gid = lane >> 2, tig = lane & 3;
    const int kt = blockIdx.x * 128, lp = blockIdx.y;
    const int b = blockIdx.z >> 1, ct = blockIdx.z & 1;
    const int c0 = ct * 64;
    const float* qp = q + (long)b * CL + (long)c0 * Lsp;
    const float* Kp = K + (long)b * C4L + (long)kt * Lsp;
    const int lbase = lp * 1024;

    const int m0b = (wid >> 2) * 32, n0b = (wid & 3) * 32;
    float acc[8][4];
#pragma unroll
    for (int i = 0; i < 8; i++)
#pragma unroll
        for (int j = 0; j < 4; j++) acc[i][j] = 0.f;

    for (int lc = 0; lc < 1024; lc += 128) {
        const int l0 = lbase + lc;
        __syncthreads();
#pragma unroll
        for (int j = 0; j < 8; j++) {       // Q: 64 rows x 32 f4
            int idx = tid + j * 256;
            int r = idx >> 5, c4 = idx & 31;
            float4 a = *(const float4*)&qp[(long)r * Lsp + l0 + c4 * 4];
            uint32_t h0, l0w, h1, l1w;
            packbf2(a.x, a.y, h0, l0w); packbf2(a.z, a.w, h1, l1w);
            *(uint2*)&Qh[r * NW + c4 * 2] = make_uint2(h0, h1);
            *(uint2*)&Ql[r * NW + c4 * 2] = make_uint2(l0w, l1w);
        }
#pragma unroll
        for (int j = 0; j < 16; j++) {      // K: 128 rows x 32 f4
            int idx = tid + j * 256;
            int r = idx >> 5, c4 = idx & 31;
            float4 kk = *(const float4*)&Kp[(long)r * Lsp + l0 + c4 * 4];
            uint32_t h0, l0w, h1, l1w;
            packbf2(kk.x, kk.y, h0, l0w); packbf2(kk.z, kk.w, h1, l1w);
            *(uint2*)&Kh[r * NW + c4 * 2] = make_uint2(h0, h1);
            *(uint2*)&Kl[r * NW + c4 * 2] = make_uint2(l0w, l1w);
        }
        __syncthreads();
#pragma unroll
        for (int k0 = 0; k0 < 128; k0 += 16) {
            const int kw = k0 / 2 + tig;
            uint32_t bh[4][2], bl[4][2];
#pragma unroll
            for (int nt = 0; nt < 4; nt++) {
                int n = n0b + nt * 8 + gid;
                bh[nt][0] = Kh[n * NW + kw];     bh[nt][1] = Kh[n * NW + kw + 4];
                bl[nt][0] = Kl[n * NW + kw];     bl[nt][1] = Kl[n * NW + kw + 4];
            }
#pragma unroll
            for (int mt = 0; mt < 2; mt++) {
                int r0 = m0b + mt * 16 + gid, r1 = r0 + 8;
                uint32_t ah[4], al[4];
                ah[0] = Qh[r0 * NW + kw];     ah[1] = Qh[r1 * NW + kw];
                ah[2] = Qh[r0 * NW + kw + 4]; ah[3] = Qh[r1 * NW + kw + 4];
                al[0] = Ql[r0 * NW + kw];     al[1] = Ql[r1 * NW + kw];
                al[2] = Ql[r0 * NW + kw + 4]; al[3] = Ql[r1 * NW + kw + 4];
#pragma unroll
                for (int nt = 0; nt < 4; nt++)
                    mma3bf(acc[mt * 4 + nt], ah, al,
                           bh[nt][0], bh[nt][1], bl[nt][0], bl[nt][1]);
            }
        }
    }
    float* ap = atp + (long)lp * (Bb * 65536) + (long)b * 65536 + (long)c0 * 512;
#pragma unroll
    for (int mt = 0; mt < 2; mt++)
#pragma unroll
        for (int nt = 0; nt < 4; nt++) {
            int m = m0b + mt * 16 + gid;
            int n = kt + n0b + nt * 8 + tig * 2;
            float* a = acc[mt * 4 + nt];
            *(float2*)&ap[(long)m * 512 + n] = make_float2(a[0], a[1]);
            *(float2*)&ap[(long)(m + 8) * 512 + n] = make_float2(a[2], a[3]);
        }
}

// ---------------------------------------------------------------------------
// masked softmax: sums 4 qk partials, scales by 1/64, writes probs
// ---------------------------------------------------------------------------
__global__ __launch_bounds__(128) void softmax_v6(
    const float* __restrict__ atp, float* __restrict__ at,
    const int* __restrict__ mask)
{
    __shared__ float sm[128];
    const int row = blockIdx.x;
    const int b = row >> 7;
    const int t = threadIdx.x;
    const float sc = 0.015625f;
    const long roff = (long)row * 512;
    const long pstr = (long)Bb * 65536;

    float v[4];
    float mx = -INFINITY;
#pragma unroll
    for (int j = 0; j < 4; j++) {
        bool on = mask[b * 4 + j] > 0;
        float sum = atp[roff + j * 128 + t] + atp[pstr + roff + j * 128 + t]
                  + atp[2 * pstr + roff + j * 128 + t] + atp[3 * pstr + roff + j * 128 + t];
        v[j] = on ? sum * sc : -INFINITY;
        mx = fmaxf(mx, v[j]);
    }
    sm[t] = mx; __syncthreads();
    for (int s = 64; s > 0; s >>= 1) {
        if (t < s) sm[t] = fmaxf(sm[t], sm[t + s]);
        __syncthreads();
    }
    mx = sm[0]; __syncthreads();

    float sum = 0.f;
#pragma unroll
    for (int j = 0; j < 4; j++) {
        v[j] = (v[j] == -INFINITY) ? 0.f : expf(v[j] - mx);
        sum += v[j];
    }
    sm[t] = sum; __syncthreads();
    for (int s = 64; s > 0; s >>= 1) {
        if (t < s) sm[t] += sm[t + s];
        __syncthreads();
    }
    float inv = 1.f / sm[0];
#pragma unroll
    for (int j = 0; j < 4; j++) at[roff + j * 128 + t] = v[j] * inv;
}

// ---------------------------------------------------------------------------
// av: x[b][c][lt+n] = sum_k attn[b][c][k] * V^T[b][lt+n][k]
// packed-bf16, tile m128c x n64l, k-chunks 64. grid (64, Bb)  (R13 proven)
// ---------------------------------------------------------------------------
#define ASTR 36
#define AV_A2 (128*ASTR)
#define AV_B2 (64*ASTR)
#define AV_SMEM ((AV_A2 + AV_B2)*8)   // 55296 B
__global__ __launch_bounds__(256, 2) void av_v9(
    const float* __restrict__ at, const float* __restrict__ vT,
    float* __restrict__ xout)
{
    extern __shared__ uint2 sm2[];
    uint2* Aa = sm2;               // attn [128][ASTR]
    uint2* Vs = sm2 + AV_A2;       // V^T  [64][ASTR]
    const int tid = threadIdx.x;
    const int lane = tid & 31, wid = tid >> 5;
    const int gid = lane >> 2, tig = lane & 3;
    const int lt = blockIdx.x * 64;
    const int b = blockIdx.y;
    const float* ap = at + (long)b * 65536;
    const float* vp = vT + (long)b * ((long)Lsp * 512);
    const int xf = (gid >> 1) & 2;

    const int m0b = (wid >> 1) * 32, n0b = (wid & 1) * 32;
    float acc[8][4];
#pragma unroll
    for (int i = 0; i < 8; i++)
#pragma unroll
        for (int j = 0; j < 4; j++) acc[i][j] = 0.f;

    for (int kg = 0; kg < 512; kg += 64) {
        __syncthreads();
#pragma unroll
        for (int j = 0; j < 8; j++) {       // attn: 128 rows x 16 f4
            int idx = tid + j * 256;
            int r = idx >> 4, c4 = idx & 15;
            float4 a = *(const float4*)&ap[(long)r * 512 + kg + c4 * 4];
            uint32_t h0, l0w, h1, l1w;
            packbf2(a.x, a.y, h0, l0w); packbf2(a.z, a.w, h1, l1w);
            *(uint4*)&Aa[r * ASTR + ((2 * c4) ^ ((r >> 1) & 2))] =
                make_uint4(h0, l0w, h1, l1w);
        }
#pragma unroll
        for (int j = 0; j < 4; j++) {       // V^T: 64 rows x 16 f4
            int idx = tid + j * 256;
            int r = idx >> 4, c4 = idx & 15;
            float4 vv = *(const float4*)&vp[(long)(lt + r) * 512 + kg + c4 * 4];
            uint32_t h0, l0w, h1, l1w;
            packbf2(vv.x, vv.y, h0, l0w); packbf2(vv.z, vv.w, h1, l1w);
            *(uint4*)&Vs[r * ASTR + ((2 * c4) ^ ((r >> 1) & 2))] =
                make_uint4(h0, l0w, h1, l1w);
        }
        __syncthreads();
#pragma unroll
        for (int k0 = 0; k0 < 64; k0 += 16) {
            const int kx = (k0 / 2 + tig) ^ xf;
            uint32_t bh[4][2], bl[4][2];
#pragma unroll
            for (int nt = 0; nt < 4; nt++) {
                int n = n0b + nt * 8 + gid;
                uint2 P0 = Vs[n * ASTR + kx];
                uint2 P1 = Vs[n * ASTR + kx + 4];
                bh[nt][0] = P0.x; bl[nt][0] = P0.y;
                bh[nt][1] = P1.x; bl[nt][1] = P1.y;
            }
#pragma unroll
            for (int mt = 0; mt < 2; mt++) {
                int r0 = m0b + mt * 16 + gid, r1 = r0 + 8;
                uint2 Pa = Aa[r0 * ASTR + kx];
                uint2 Pb = Aa[r1 * ASTR + kx];
                uint2 Pc = Aa[r0 * ASTR + kx + 4];
                uint2 Pd = Aa[r1 * ASTR + kx + 4];
                uint32_t ah[4] = {Pa.x, Pb.x, Pc.x, Pd.x};
                uint32_t al[4] = {Pa.y, Pb.y, Pc.y, Pd.y};
#pragma unroll
                for (int nt = 0; nt < 4; nt++)
                    mma3bf(acc[mt * 4 + nt], ah, al,
                           bh[nt][0], bh[nt][1], bl[nt][0], bl[nt][1]);
            }
        }
    }
    float* xp = xout + (long)b * CL + lt;
#pragma unroll
    for (int mt = 0; mt < 2; mt++)
#pragma unroll
        for (int nt = 0; nt < 4; nt++) {
            int m = m0b + mt * 16 + gid;
            int n = n0b + nt * 8 + tig * 2;
            float* a = acc[mt * 4 + nt];
            *(float2*)&xp[(long)m * Lsp + n] = make_float2(a[0], a[1]);
            *(float2*)&xp[(long)(m + 8) * Lsp + n] = make_float2(a[2], a[3]);
        }
}

// ---------------------------------------------------------------------------
// Depthwise 3x3x3 + bias, float4 loads
// ---------------------------------------------------------------------------
__global__ __launch_bounds__(256) void dw_v3(
    const float* __restrict__ inb, float* __restrict__ outb,
    long iz, long ib,
    const float* __restrict__ w27b, const float* __restrict__ biasb, int blk0)
{
    __shared__ float sp[16 * 324];
    const int tid = threadIdx.x;
    const int x = tid & 15, y = tid >> 4;
    const int c = blockIdx.x, b = blockIdx.y, z = blockIdx.z;
    const int blk = blk0 + z;

    const float* in = inb + (long)z * iz + (long)b * ib + (long)c * Lsp;
    float* out = outb + (long)z * iz + (long)b * ib + (long)c * Lsp;
    const float* wv = w27b + (long)blk * Cch * 27 + c * 27;
    const float bias = biasb[blk * Cch + c];

    for (int idx = tid; idx < 16 * 324; idx += 256) sp[idx] = 0.f;
    __syncthreads();
    const float4* in4 = (const float4*)in;
#pragma unroll
    for (int j = 0; j < 4; j++) {
        int i4 = tid + j * 256;
        float4 vv = in4[i4];
        int zz = i4 >> 6, rem = i4 & 63;
        float* dst = &sp[zz * 324 + ((rem >> 2) + 1) * 18 + (rem & 3) * 4 + 1];
        dst[0] = vv.x; dst[1] = vv.y; dst[2] = vv.z; dst[3] = vv.w;
    }
    float w[27];
#pragma unroll
    for (int k = 0; k < 27; k++) w[k] = wv[k];
    __syncthreads();

    float p0[9], p1[9], p2[9];
#pragma unroll
    for (int k = 0; k < 9; k++) p0[k] = 0.f;
#pragma unroll
    for (int dy = 0; dy < 3; dy++)
#pragma unroll
        for (int dx = 0; dx < 3; dx++)
            p1[dy * 3 + dx] = sp[(y + dy) * 18 + (x + dx)];

#pragma unroll
    for (int zz = 0; zz < 16; zz++) {
        if (zz < 15) {
#pragma unroll
            for (int dy = 0; dy < 3; dy++)
#pragma unroll
                for (int dx = 0; dx < 3; dx++)
                    p2[dy * 3 + dx] = sp[(zz + 1) * 324 + (y + dy) * 18 + (x + dx)];
        } else {
#pragma unroll
            for (int k = 0; k < 9; k++) p2[k] = 0.f;
        }
        float a = bias;
#pragma unroll
        for (int k = 0; k < 9; k++) a += p0[k] * w[k];
#pragma unroll
        for (int k = 0; k < 9; k++) a += p1[k] * w[9 + k];
#pragma unroll
        for (int k = 0; k < 9; k++) a += p2[k] * w[18 + k];
        out[zz * 256 + tid] = a;
#pragma unroll
        for (int k = 0; k < 9; k++) { p0[k] = p1[k]; p1[k] = p2[k]; }
    }
}

// ---------------------------------------------------------------------------
extern "C" void kernel_launch(void* const* d_in, const int* in_sizes, int n_in,
                              void* d_out, int out_size)
{
    const float* query = (const float*)d_in[0];
    const float* m0 = (const float*)d_in[1];
    const float* m1 = (const float*)d_in[2];
    const float* m2 = (const float*)d_in[3];
    const float* m3 = (const float*)d_in[4];
    const int*   mask  = (const int*)d_in[5];
    const float* pw1_w = (const float*)d_in[6];
    const float* pw1_b = (const float*)d_in[7];
    const float* ln1_g = (const float*)d_in[8];
    const float* ln1_b = (const float*)d_in[9];
    const float* dw_w  = (const float*)d_in[10];
    const float* dw_b  = (const float*)d_in[11];
    const float* ln2_g = (const float*)d_in[12];
    const float* ln2_b = (const float*)d_in[13];
    const float* pw2_w = (const float*)d_in[14];
    const float* pw2_b = (const float*)d_in[15];
    const float* ln3_g = (const float*)d_in[16];
    const float* ln3_b = (const float*)d_in[17];
    float* out = (float*)d_out;

    float *y1, *y2, *qb, *kv, *xb, *at, *atp;
    cudaGetSymbolAddress((void**)&y1, g_y1);
    cudaGetSymbolAddress((void**)&y2, g_y2);
    cudaGetSymbolAddress((void**)&qb, g_q);
    cudaGetSymbolAddress((void**)&kv, g_KV);
    cudaGetSymbolAddress((void**)&xb, g_x);
    cudaGetSymbolAddress((void**)&at, g_at);
    cudaGetSymbolAddress((void**)&atp, g_atp);
    float* Kb = kv;
    float* Vt = kv + (long)Bb * C4L;

    cudaFuncSetAttribute(pw_v12, cudaFuncAttributeMaxDynamicSharedMemorySize, PW_SMEM);
    cudaFuncSetAttribute(qk_v8, cudaFuncAttributeMaxDynamicSharedMemorySize, QK_SMEM);
    cudaFuncSetAttribute(av_v9, cudaFuncAttributeMaxDynamicSharedMemorySize, AV_SMEM);

    // ---- weight prepack (separate hi/lo planes matching pw smem layout) ----
    prep_w<<<20, 256>>>(pw1_w, pw2_w);

    // ---- blocks 0..8 (query + K/V maps) ----
    pw_v12<<<dim3(64, Bb, 9), 256, PW_SMEM>>>(
        query, m0, m1, m2, m3, /*imode=*/1, /*wofs=*/0,
        pw1_b, ln1_g, ln1_b, ln1_g, ln1_b, /*blk0=*/0,
        nullptr, y1, nullptr, /*omode=*/1, /*flags=*/2);
    dw_v3<<<dim3(Cch, Bb, 9), 256>>>(y1, y2, BCL, CL, dw_w, dw_b, 0);
    pw_v12<<<dim3(64, Bb, 9), 256, PW_SMEM>>>(
        y2, nullptr, nullptr, nullptr, nullptr, /*imode=*/2, /*wofs=*/10,
        pw2_b, ln2_g, ln2_b, ln3_g, ln3_b, /*blk0=*/0,
        nullptr, qb, kv, /*omode=*/2, /*flags=*/1);

    // ---- attention ----
    qk_v8<<<dim3(4, 4, 16), 256, QK_SMEM>>>(qb, Kb, atp);
    softmax_v6<<<Bb * 128, 128>>>(atp, at, mask);
    av_v9<<<dim3(64, Bb), 256, AV_SMEM>>>(at, Vt, xb);

    // ---- out_project (blk 9) + residual ----
    pw_v12<<<dim3(64, Bb, 1), 256, PW_SMEM>>>(
        xb, nullptr, nullptr, nullptr, nullptr, /*imode=*/0, /*wofs=*/0,
        pw1_b, ln1_g, ln1_b, ln1_g, ln1_b, /*blk0=*/9,
        nullptr, y1, nullptr, /*omode=*/0, /*flags=*/2);
    dw_v3<<<dim3(Cch, Bb, 1), 256>>>(y1, y2, BCL, CL, dw_w, dw_b, 9);
    pw_v12<<<dim3(64, Bb, 1), 256, PW_SMEM>>>(
        y2, nullptr, nullptr, nullptr, nullptr, /*imode=*/0, /*wofs=*/10,
        pw2_b, ln2_g, ln2_b, ln3_g, ln3_b, /*blk0=*/9,
        query, out, nullptr, /*omode=*/0, /*flags=*/1 | 4);
}

// round 16
// speedup vs baseline: 1.2865x; 1.0052x over previous
#include <cuda_runtime.h>
#include <math.h>
#include <stdint.h>

#define Bb   8
#define Cch  128
#define Lsp  4096
#define CL   (Cch*Lsp)        // 524288
#define C4L  (4*CL)
#define BCL  (Bb*CL)

// ---------------- scratch (static device memory) ----------------------------
__device__ float g_y1[9*BCL];
__device__ float g_y2[9*BCL];
__device__ float g_q [BCL];
__device__ float g_KV[2*Bb*C4L];          // K: [B][4C][L] ; V^T: [B][L][4C]
__device__ float g_x [BCL];
__device__ float g_at [Bb*128*512];       // softmax probs
__device__ float g_atp[4*Bb*128*512];     // qk partials (4 L-parts)
__device__ uint32_t g_Wpk[20*2*128*68];   // prepacked W: per-matrix Wh plane | Wl plane

__device__ __forceinline__ float gelu_exact(float x) {
    return 0.5f * x * (1.0f + erff(x * 0.70710678118654752f));
}

// ---- cp.async helpers -------------------------------------------------------
#define CP_ASYNC16(dst_u32, src_ptr) \
    asm volatile("cp.async.cg.shared.global [%0], [%1], 16;" \
                 :: "r"(dst_u32), "l"(src_ptr) : "memory")
#define CP_COMMIT() asm volatile("cp.async.commit_group;" ::: "memory")
#define CP_WAIT0()  asm volatile("cp.async.wait_group 0;" ::: "memory")

// ---- ldmatrix: 4 x (8x8 b16) tiles ------------------------------------------
#define LDSM4(r0, r1, r2, r3, addr) \
    asm volatile("ldmatrix.sync.aligned.m8n8.x4.shared.b16 {%0,%1,%2,%3}, [%4];" \
                 : "=r"(r0), "=r"(r1), "=r"(r2), "=r"(r3) : "r"(addr))

// ======================= bf16 hi/lo split-pack ==============================
__device__ __forceinline__ void packbf2(float x0, float x1, uint32_t& h, uint32_t& l) {
    asm("cvt.rn.bf16x2.f32 %0, %1, %2;" : "=r"(h) : "f"(x1), "f"(x0));
    float h0 = __uint_as_float(h << 16);
    float h1 = __uint_as_float(h & 0xffff0000u);
    asm("cvt.rn.bf16x2.f32 %0, %1, %2;" : "=r"(l) : "f"(x1 - h1), "f"(x0 - h0));
}

__device__ __forceinline__ void mmabf(float* d,
    uint32_t a0, uint32_t a1, uint32_t a2, uint32_t a3, uint32_t b0, uint32_t b1)
{
    asm volatile(
        "mma.sync.aligned.m16n8k16.row.col.f32.bf16.bf16.f32 "
        "{%0,%1,%2,%3}, {%4,%5,%6,%7}, {%8,%9}, {%0,%1,%2,%3};"
        : "+f"(d[0]), "+f"(d[1]), "+f"(d[2]), "+f"(d[3])
        : "r"(a0), "r"(a1), "r"(a2), "r"(a3), "r"(b0), "r"(b1));
}
__device__ __forceinline__ void mma3bf(float* d,
    const uint32_t* ah, const uint32_t* al,
    uint32_t bh0, uint32_t bh1, uint32_t bl0, uint32_t bl1)
{
    mmabf(d, ah[0], ah[1], ah[2], ah[3], bl0, bl1);
    mmabf(d, al[0], al[1], al[2], al[3], bh0, bh1);
    mmabf(d, ah[0], ah[1], ah[2], ah[3], bh0, bh1);
}

// ---------------------------------------------------------------------------
// Weight prepack: [o][c] fp32 -> Wh plane [128][68] then Wl plane [128][68].
// ---------------------------------------------------------------------------
__global__ __launch_bounds__(256) void prep_w(
    const float* __restrict__ w1, const float* __restrict__ w2)
{
    const int mi = blockIdx.x;
    const float* src = mi < 10 ? w1 + (long)mi * 16384 : w2 + (long)(mi - 10) * 16384;
    uint32_t* dh = g_Wpk + (long)mi * 17408;
    uint32_t* dl = dh + 8704;
    const int tid = threadIdx.x;
#pragma unroll
    for (int i = 0; i < 16; i++) {
        int idx = tid + i * 256;
        int o = idx >> 5, c4 = idx & 31;
        float4 w = *(const float4*)&src[o * 128 + c4 * 4];
        uint32_t h0, l0, h1, l1;
        packbf2(w.x, w.y, h0, l0);
        packbf2(w.z, w.w, h1, l1);
        *(uint2*)&dh[o * 68 + c4 * 2] = make_uint2(h0, h1);
        *(uint2*)&dl[o * 68 + c4 * 2] = make_uint2(l0, l1);
    }
    for (int i = tid; i < 512; i += 256) {
        int o = i >> 2, w = 64 + (i & 3);
        dh[o * 68 + w] = 0; dl[o * 68 + w] = 0;
    }
}

// ---------------------------------------------------------------------------
// Fused pointwise block: 64-token x 128-out tile, 256 threads, 2 CTAs/SM.
// ldmatrix mainloop + prepacked-W cp.async + smem LN params.
// ---------------------------------------------------------------------------
#define NW 68
#define AW (64*NW)
#define WW (128*NW)
#define CS_STR 132
#define PW_SMEM ((2*AW + 2*WW + 512 + 640) * 4)   // 109056 B

__global__ __launch_bounds__(256, 2) void pw_v13(
    const float* __restrict__ inq,
    const float* __restrict__ mm0, const float* __restrict__ mm1,
    const float* __restrict__ mm2, const float* __restrict__ mm3,
    int imode, int wofs,
    const float* __restrict__ biasb,
    const float* __restrict__ g1b, const float* __restrict__ b1b,
    const float* __restrict__ g2b, const float* __restrict__ b2b,
    int blk0,
    const float* __restrict__ res,
    float* __restrict__ out0, float* __restrict__ out1, int omode,
    int flags)
{
    extern __shared__ uint32_t smu[];
    uint32_t* Ah = smu;                // [64][NW]
    uint32_t* Al = smu + AW;
    uint32_t* Wh = smu + 2 * AW;       // [128][NW]  (Wh || Wl contiguous)
    float* red = (float*)(smu + 2 * AW + 2 * WW);
    float* ps  = red + 512;            // bias | go | bo | gi | bi
    float* Cs  = (float*)smu;          // epilogue alias

    const int tid = threadIdx.x;
    const int lane = tid & 31, wid = tid >> 5;
    const int t = tid & 63, p = tid >> 6;
    const int cb = p * 32;
    const int b = blockIdx.y, z = blockIdx.z;
    const int l0 = blockIdx.x * 64;
    const int blk = blk0 + z;

    const float* src;
    if (imode == 0) src = inq;
    else if (imode == 1) {
        if (z == 0) src = inq;
        else { int zs = (z - 1) & 3; src = zs == 0 ? mm0 : zs == 1 ? mm1 : zs == 2 ? mm2 : mm3; }
    } else src = inq + (long)z * BCL;
    const float* inp = src + (long)b * CL + l0;

    const float* bias = biasb + blk * 128;
    const float* gi = g1b + blk * 128, *bi = b1b + blk * 128;
    const float* go = g2b + blk * 128, *bo = b2b + blk * 128;

    // ---- W staging: cp.async from prepacked global ----
    {
        const char* wsrc = (const char*)(g_Wpk + (long)(wofs + blk) * 17408) + tid * 16;
        uint32_t wdst = (uint32_t)__cvta_generic_to_shared((const char*)Wh + tid * 16);
#pragma unroll
        for (int i = 0; i < 17; i++)
            CP_ASYNC16(wdst + i * 4096, wsrc + (long)i * 4096);
        CP_COMMIT();
    }
    if (tid < 128) {
        ps[tid] = bias[tid]; ps[128 + tid] = go[tid]; ps[256 + tid] = bo[tid];
        ps[384 + tid] = gi[tid]; ps[512 + tid] = bi[tid];
    }

    // ---- A loads ----
    float v[32];
    float s = 0.f, q = 0.f;
#pragma unroll
    for (int i = 0; i < 32; i++) {
        v[i] = inp[(long)(cb + i) * Lsp + t];
        s += v[i]; q += v[i] * v[i];
    }

    if (flags & 1) {
        red[p * 64 + t] = s; red[256 + p * 64 + t] = q;
        __syncthreads();
        float S = red[t] + red[64 + t] + red[128 + t] + red[192 + t];
        float Q = red[256 + t] + red[320 + t] + red[384 + t] + red[448 + t];
        float mean = S * (1.f / 128.f);
        float rstd = rsqrtf(Q * (1.f / 128.f) - mean * mean + 1e-6f);
#pragma unroll
        for (int i = 0; i < 16; i++) {
            float x0 = gelu_exact((v[2*i]   - mean) * rstd * ps[384 + cb + 2*i]   + ps[512 + cb + 2*i]);
            float x1 = gelu_exact((v[2*i+1] - mean) * rstd * ps[384 + cb + 2*i+1] + ps[512 + cb + 2*i+1]);
            uint32_t h, l;
            packbf2(x0, x1, h, l);
            Ah[t * NW + cb / 2 + i] = h;
            Al[t * NW + cb / 2 + i] = l;
        }
    } else {
#pragma unroll
        for (int i = 0; i < 16; i++) {
            uint32_t h, l;
            packbf2(v[2*i], v[2*i+1], h, l);
            Ah[t * NW + cb / 2 + i] = h;
            Al[t * NW + cb / 2 + i] = l;
        }
    }
    CP_WAIT0();
    __syncthreads();

    // ---- mainloop: ldmatrix (8 per step) + 24 MMA ----
    const int m0b = (wid >> 2) * 32, n0b = (wid & 3) * 32;
    const uint32_t smBase = (uint32_t)__cvta_generic_to_shared(smu);
    // A addresses: rows r0 + (lane&15), k-half (lane>>4)*4 words
    uint32_t aAh0 = smBase + ((m0b + (lane & 15)) * NW + (lane >> 4) * 4) * 4;
    uint32_t aAh1 = aAh0 + 16 * NW * 4;
    uint32_t aAl0 = aAh0 + AW * 4;
    uint32_t aAl1 = aAh1 + AW * 4;
    // B addresses: n = n0b + 16g + (lane>>4)*8 + (lane&7), col ((lane>>3)&1)*4
    const int nrow = (lane >> 4) * 8 + (lane & 7);
    const int ncol = ((lane >> 3) & 1) * 4;
    uint32_t bWh0 = smBase + (2 * AW + (n0b + nrow) * NW + ncol) * 4;
    uint32_t bWh1 = bWh0 + 16 * NW * 4;
    uint32_t bWl0 = bWh0 + WW * 4;
    uint32_t bWl1 = bWh1 + WW * 4;

    float acc[8][4];
#pragma unroll
    for (int i = 0; i < 8; i++)
#pragma unroll
        for (int j = 0; j < 4; j++) acc[i][j] = 0.f;

#pragma unroll
    for (int k0 = 0; k0 < 128; k0 += 16) {
        const uint32_t ko = k0 * 2;      // k0/2 words * 4 bytes
        uint32_t bh[4][2], bl[4][2];
        LDSM4(bh[0][0], bh[0][1], bh[1][0], bh[1][1], bWh0 + ko);
        LDSM4(bh[2][0], bh[2][1], bh[3][0], bh[3][1], bWh1 + ko);
        LDSM4(bl[0][0], bl[0][1], bl[1][0], bl[1][1], bWl0 + ko);
        LDSM4(bl[2][0], bl[2][1], bl[3][0], bl[3][1], bWl1 + ko);
        uint32_t ah[2][4], al[2][4];
        LDSM4(ah[0][0], ah[0][1], ah[0][2], ah[0][3], aAh0 + ko);
        LDSM4(al[0][0], al[0][1], al[0][2], al[0][3], aAl0 + ko);
        LDSM4(ah[1][0], ah[1][1], ah[1][2], ah[1][3], aAh1 + ko);
        LDSM4(al[1][0], al[1][1], al[1][2], al[1][3], aAl1 + ko);
#pragma unroll
        for (int mt = 0; mt < 2; mt++)
#pragma unroll
            for (int nt = 0; nt < 4; nt++)
                mma3bf(acc[mt * 4 + nt], ah[mt], al[mt],
                       bh[nt][0], bh[nt][1], bl[nt][0], bl[nt][1]);
    }
    __syncthreads();

    // ---- C -> smem (alias A region) ----
    const int gid = lane >> 2, tig = lane & 3;
#pragma unroll
    for (int mt = 0; mt < 2; mt++)
#pragma unroll
        for (int nt = 0; nt < 4; nt++) {
            int m = m0b + mt * 16 + gid, n = n0b + nt * 8 + tig * 2;
            float* a = acc[mt * 4 + nt];
            *(float2*)&Cs[m * CS_STR + n] = make_float2(a[0], a[1]);
            *(float2*)&Cs[(m + 8) * CS_STR + n] = make_float2(a[2], a[3]);
        }
    __syncthreads();

    // ---- epilogue ----
    float w2[32];
    float s2 = 0.f, q2 = 0.f;
#pragma unroll
    for (int i = 0; i < 32; i++) {
        w2[i] = Cs[t * CS_STR + cb + i] + ps[cb + i];
        s2 += w2[i]; q2 += w2[i] * w2[i];
    }
    red[p * 64 + t] = s2; red[256 + p * 64 + t] = q2;
    __syncthreads();
    float S2 = red[t] + red[64 + t] + red[128 + t] + red[192 + t];
    float Q2 = red[256 + t] + red[320 + t] + red[384 + t] + red[448 + t];
    float mean2 = S2 * (1.f / 128.f);
    float rstd2 = rsqrtf(Q2 * (1.f / 128.f) - mean2 * mean2 + 1e-6f);
    const float* resp = (flags & 4) ? (res + (long)b * CL + l0) : nullptr;
    float buf[32];
#pragma unroll
    for (int i = 0; i < 32; i++) {
        int c = cb + i;
        float val = (w2[i] - mean2) * rstd2 * ps[128 + c] + ps[256 + c];
        if (flags & 2) val = gelu_exact(val);
        if (flags & 4) val += resp[(long)c * Lsp + t];
        buf[i] = val;
    }
    if (omode == 2 && z >= 5) {
        float* vp = out1 + (long)Bb * C4L + (long)b * ((long)Lsp * 512)
                  + (long)(l0 + t) * 512 + (z - 5) * 128 + cb;
#pragma unroll
        for (int j = 0; j < 8; j++)
            *(float4*)&vp[4 * j] = make_float4(buf[4*j], buf[4*j+1], buf[4*j+2], buf[4*j+3]);
    } else {
        float* outp;
        if (omode == 0) outp = out0 + (long)b * CL + l0;
        else if (omode == 1) outp = out0 + (long)z * BCL + (long)b * CL + l0;
        else if (z == 0) outp = out0 + (long)b * CL + l0;
        else outp = out1 + (long)(z - 1) * CL + (long)b * C4L + l0;
#pragma unroll
        for (int i = 0; i < 32; i++)
            outp[(long)(cb + i) * Lsp + t] = buf[i];
    }
}

// ---------------------------------------------------------------------------
// qk partial: 64c x 128k tile, ldmatrix mainloop. grid (4 kt, 4 lp, 16)
// ---------------------------------------------------------------------------
#define QK_SMEM ((2*AW + 2*WW) * 4)   // 104448 B
__global__ __launch_bounds__(256, 2) void qk_v10(
    const float* __restrict__ q, const float* __restrict__ K,
    float* __restrict__ atp)
{
    extern __shared__ uint32_t smu[];
    uint32_t* Qh = smu;                // [64][NW]
    uint32_t* Ql = smu + AW;
    uint32_t* Kh = smu + 2 * AW;       // [128][NW]
    uint32_t* Kl = smu + 2 * AW + WW;
    const int tid = threadIdx.x;
    const int lane = tid & 31, wid = tid >> 5;
    const int gid = lane >> 2, tig = lane & 3;
    const int kt = blockIdx.x * 128, lp = blockIdx.y;
    const int b = blockIdx.z >> 1, ct = blockIdx.z & 1;
    const int c0 = ct * 64;
    const float* qp = q + (long)b * CL + (long)c0 * Lsp;
    const float* Kp = K + (long)b * C4L + (long)kt * Lsp;
    const int lbase = lp * 1024;

    const int m0b = (wid >> 2) * 32, n0b = (wid & 3) * 32;
    const uint32_t smBase = (uint32_t)__cvta_generic_to_shared(smu);
    uint32_t aQh0 = smBase + ((m0b + (lane & 15)) * NW + (lane >> 4) * 4) * 4;
    uint32_t aQh1 = aQh0 + 16 * NW * 4;
    uint32_t aQl0 = aQh0 + AW * 4;
    uint32_t aQl1 = aQh1 + AW * 4;
    const int nrow = (lane >> 4) * 8 + (lane & 7);
    const int ncol = ((lane >> 3) & 1) * 4;
    uint32_t bKh0 = smBase + (2 * AW + (n0b + nrow) * NW + ncol) * 4;
    uint32_t bKh1 = bKh0 + 16 * NW * 4;
    uint32_t bKl0 = bKh0 + WW * 4;
    uint32_t bKl1 = bKh1 + WW * 4;

    float acc[8][4];
#pragma unroll
    for (int i = 0; i < 8; i++)
#pragma unroll
        for (int j = 0; j < 4; j++) acc[i][j] = 0.f;

    for (int lc = 0; lc < 1024; lc += 128) {
        const int l0 = lbase + lc;
        __syncthreads();
#pragma unroll
        for (int j = 0; j < 8; j++) {       // Q: 64 rows x 32 f4
            int idx = tid + j * 256;
            int r = idx >> 5, c4 = idx & 31;
            float4 a = *(const float4*)&qp[(long)r * Lsp + l0 + c4 * 4];
            uint32_t h0, l0w, h1, l1w;
            packbf2(a.x, a.y, h0, l0w); packbf2(a.z, a.w, h1, l1w);
            *(uint2*)&Qh[r * NW + c4 * 2] = make_uint2(h0, h1);
            *(uint2*)&Ql[r * NW + c4 * 2] = make_uint2(l0w, l1w);
        }
#pragma unroll
        for (int j = 0; j < 16; j++) {      // K: 128 rows x 32 f4
            int idx = tid + j * 256;
            int r = idx >> 5, c4 = idx & 31;
            float4 kk = *(const float4*)&Kp[(long)r * Lsp + l0 + c4 * 4];
            uint32_t h0, l0w, h1, l1w;
            packbf2(kk.x, kk.y, h0, l0w); packbf2(kk.z, kk.w, h1, l1w);
            *(uint2*)&Kh[r * NW + c4 * 2] = make_uint2(h0, h1);
            *(uint2*)&Kl[r * NW + c4 * 2] = make_uint2(l0w, l1w);
        }
        __syncthreads();
#pragma unroll
        for (int k0 = 0; k0 < 128; k0 += 16) {
            const uint32_t ko = k0 * 2;
            uint32_t bh[4][2], bl[4][2];
            LDSM4(bh[0][0], bh[0][1], bh[1][0], bh[1][1], bKh0 + ko);
            LDSM4(bh[2][0], bh[2][1], bh[3][0], bh[3][1], bKh1 + ko);
            LDSM4(bl[0][0], bl[0][1], bl[1][0], bl[1][1], bKl0 + ko);
            LDSM4(bl[2][0], bl[2][1], bl[3][0], bl[3][1], bKl1 + ko);
            uint32_t ah[2][4], al[2][4];
            LDSM4(ah[0][0], ah[0][1], ah[0][2], ah[0][3], aQh0 + ko);
            LDSM4(al[0][0], al[0][1], al[0][2], al[0][3], aQl0 + ko);
            LDSM4(ah[1][0], ah[1][1], ah[1][2], ah[1][3], aQh1 + ko);
            LDSM4(al[1][0], al[1][1], al[1][2], al[1][3], aQl1 + ko);
#pragma unroll
            for (int mt = 0; mt < 2; mt++)
#pragma unroll
                for (int nt = 0; nt < 4; nt++)
                    mma3bf(acc[mt * 4 + nt], ah[mt], al[mt],
                           bh[nt][0], bh[nt][1], bl[nt][0], bl[nt][1]);
        }
    }
    float* ap = atp + (long)lp * (Bb * 65536) + (long)b * 65536 + (long)c0 * 512;
#pragma unroll
    for (int mt = 0; mt < 2; mt++)
#pragma unroll
        for (int nt = 0; nt < 4; nt++) {
            int m = m0b + mt * 16 + gid;
            int n = kt + n0b + nt * 8 + tig * 2;
            float* a = acc[mt * 4 + nt];
            *(float2*)&ap[(long)m * 512 + n] = make_float2(a[0], a[1]);
            *(float2*)&ap[(long)(m + 8) * 512 + n] = make_float2(a[2], a[3]);
        }
}

// ---------------------------------------------------------------------------
// masked softmax: sums 4 qk partials, scales by 1/64, writes probs
// ---------------------------------------------------------------------------
__global__ __launch_bounds__(128) void softmax_v6(
    const float* __restrict__ atp, float* __restrict__ at,
    const int* __restrict__ mask)
{
    __shared__ float sm[128];
    const int row = blockIdx.x;
    const int b = row >> 7;
    const int t = threadIdx.x;
    const float sc = 0.015625f;
    const long roff = (long)row * 512;
    const long pstr = (long)Bb * 65536;

    float v[4];
    float mx = -INFINITY;
#pragma unroll
    for (int j = 0; j < 4; j++) {
        bool on = mask[b * 4 + j] > 0;
        float sum = atp[roff + j * 128 + t] + atp[pstr + roff + j * 128 + t]
                  + atp[2 * pstr + roff + j * 128 + t] + atp[3 * pstr + roff + j * 128 + t];
        v[j] = on ? sum * sc : -INFINITY;
        mx = fmaxf(mx, v[j]);
    }
    sm[t] = mx; __syncthreads();
    for (int s = 64; s > 0; s >>= 1) {
        if (t < s) sm[t] = fmaxf(sm[t], sm[t + s]);
        __syncthreads();
    }
    mx = sm[0]; __syncthreads();

    float sum = 0.f;
#pragma unroll
    for (int j = 0; j < 4; j++) {
        v[j] = (v[j] == -INFINITY) ? 0.f : expf(v[j] - mx);
        sum += v[j];
    }
    sm[t] = sum; __syncthreads();
    for (int s = 64; s > 0; s >>= 1) {
        if (t < s) sm[t] += sm[t + s];
        __syncthreads();
    }
    float inv = 1.f / sm[0];
#pragma unroll
    for (int j = 0; j < 4; j++) at[roff + j * 128 + t] = v[j] * inv;
}

// ---------------------------------------------------------------------------
// av: x[b][c][lt+n] = sum_k attn[b][c][k] * V^T[b][lt+n][k]  (R13 proven)
// ---------------------------------------------------------------------------
#define ASTR 36
#define AV_A2 (128*ASTR)
#define AV_B2 (64*ASTR)
#define AV_SMEM ((AV_A2 + AV_B2)*8)   // 55296 B
__global__ __launch_bounds__(256, 2) void av_v9(
    const float* __restrict__ at, const float* __restrict__ vT,
    float* __restrict__ xout)
{
    extern __shared__ uint2 sm2[];
    uint2* Aa = sm2;               // attn [128][ASTR]
    uint2* Vs = sm2 + AV_A2;       // V^T  [64][ASTR]
    const int tid = threadIdx.x;
    const int lane = tid & 31, wid = tid >> 5;
    const int gid = lane >> 2, tig = lane & 3;
    const int lt = blockIdx.x * 64;
    const int b = blockIdx.y;
    const float* ap = at + (long)b * 65536;
    const float* vp = vT + (long)b * ((long)Lsp * 512);
    const int xf = (gid >> 1) & 2;

    const int m0b = (wid >> 1) * 32, n0b = (wid & 1) * 32;
    float acc[8][4];
#pragma unroll
    for (int i = 0; i < 8; i++)
#pragma unroll
        for (int j = 0; j < 4; j++) acc[i][j] = 0.f;

    for (int kg = 0; kg < 512; kg += 64) {
        __syncthreads();
#pragma unroll
        for (int j = 0; j < 8; j++) {
            int idx = tid + j * 256;
            int r = idx >> 4, c4 = idx & 15;
            float4 a = *(const float4*)&ap[(long)r * 512 + kg + c4 * 4];
            uint32_t h0, l0w, h1, l1w;
            packbf2(a.x, a.y, h0, l0w); packbf2(a.z, a.w, h1, l1w);
            *(uint4*)&Aa[r * ASTR + ((2 * c4) ^ ((r >> 1) & 2))] =
                make_uint4(h0, l0w, h1, l1w);
        }
#pragma unroll
        for (int j = 0; j < 4; j++) {
            int idx = tid + j * 256;
            int r = idx >> 4, c4 = idx & 15;
            float4 vv = *(const float4*)&vp[(long)(lt + r) * 512 + kg + c4 * 4];
            uint32_t h0, l0w, h1, l1w;
            packbf2(vv.x, vv.y, h0, l0w); packbf2(vv.z, vv.w, h1, l1w);
            *(uint4*)&Vs[r * ASTR + ((2 * c4) ^ ((r >> 1) & 2))] =
                make_uint4(h0, l0w, h1, l1w);
        }
        __syncthreads();
#pragma unroll
        for (int k0 = 0; k0 < 64; k0 += 16) {
            const int kx = (k0 / 2 + tig) ^ xf;
            uint32_t bh[4][2], bl[4][2];
#pragma unroll
            for (int nt = 0; nt < 4; nt++) {
                int n = n0b + nt * 8 + gid;
                uint2 P0 = Vs[n * ASTR + kx];
                uint2 P1 = Vs[n * ASTR + kx + 4];
                bh[nt][0] = P0.x; bl[nt][0] = P0.y;
                bh[nt][1] = P1.x; bl[nt][1] = P1.y;
            }
#pragma unroll
            for (int mt = 0; mt < 2; mt++) {
                int r0 = m0b + mt * 16 + gid, r1 = r0 + 8;
                uint2 Pa = Aa[r0 * ASTR + kx];
                uint2 Pb = Aa[r1 * ASTR + kx];
                uint2 Pc = Aa[r0 * ASTR + kx + 4];
                uint2 Pd = Aa[r1 * ASTR + kx + 4];
                uint32_t ah[4] = {Pa.x, Pb.x, Pc.x, Pd.x};
                uint32_t al[4] = {Pa.y, Pb.y, Pc.y, Pd.y};
#pragma unroll
                for (int nt = 0; nt < 4; nt++)
                    mma3bf(acc[mt * 4 + nt], ah, al,
                           bh[nt][0], bh[nt][1], bl[nt][0], bl[nt][1]);
            }
        }
    }
    float* xp = xout + (long)b * CL + lt;
#pragma unroll
    for (int mt = 0; mt < 2; mt++)
#pragma unroll
        for (int nt = 0; nt < 4; nt++) {
            int m = m0b + mt * 16 + gid;
            int n = n0b + nt * 8 + tig * 2;
            float* a = acc[mt * 4 + nt];
            *(float2*)&xp[(long)m * Lsp + n] = make_float2(a[0], a[1]);
            *(float2*)&xp[(long)(m + 8) * Lsp + n] = make_float2(a[2], a[3]);
        }
}

// ---------------------------------------------------------------------------
// Depthwise 3x3x3 + bias, float4 loads
// ---------------------------------------------------------------------------
__global__ __launch_bounds__(256) void dw_v3(
    const float* __restrict__ inb, float* __restrict__ outb,
    long iz, long ib,
    const float* __restrict__ w27b, const float* __restrict__ biasb, int blk0)
{
    __shared__ float sp[16 * 324];
    const int tid = threadIdx.x;
    const int x = tid & 15, y = tid >> 4;
    const int c = blockIdx.x, b = blockIdx.y, z = blockIdx.z;
    const int blk = blk0 + z;

    const float* in = inb + (long)z * iz + (long)b * ib + (long)c * Lsp;
    float* out = outb + (long)z * iz + (long)b * ib + (long)c * Lsp;
    const float* wv = w27b + (long)blk * Cch * 27 + c * 27;
    const float bias = biasb[blk * Cch + c];

    for (int idx = tid; idx < 16 * 324; idx += 256) sp[idx] = 0.f;
    __syncthreads();
    const float4* in4 = (const float4*)in;
#pragma unroll
    for (int j = 0; j < 4; j++) {
        int i4 = tid + j * 256;
        float4 vv = in4[i4];
        int zz = i4 >> 6, rem = i4 & 63;
        float* dst = &sp[zz * 324 + ((rem >> 2) + 1) * 18 + (rem & 3) * 4 + 1];
        dst[0] = vv.x; dst[1] = vv.y; dst[2] = vv.z; dst[3] = vv.w;
    }
    float w[27];
#pragma unroll
    for (int k = 0; k < 27; k++) w[k] = wv[k];
    __syncthreads();

    float p0[9], p1[9], p2[9];
#pragma unroll
    for (int k = 0; k < 9; k++) p0[k] = 0.f;
#pragma unroll
    for (int dy = 0; dy < 3; dy++)
#pragma unroll
        for (int dx = 0; dx < 3; dx++)
            p1[dy * 3 + dx] = sp[(y + dy) * 18 + (x + dx)];

#pragma unroll
    for (int zz = 0; zz < 16; zz++) {
        if (zz < 15) {
#pragma unroll
            for (int dy = 0; dy < 3; dy++)
#pragma unroll
                for (int dx = 0; dx < 3; dx++)
                    p2[dy * 3 + dx] = sp[(zz + 1) * 324 + (y + dy) * 18 + (x + dx)];
        } else {
#pragma unroll
            for (int k = 0; k < 9; k++) p2[k] = 0.f;
        }
        float a = bias;
#pragma unroll
        for (int k = 0; k < 9; k++) a += p0[k] * w[k];
#pragma unroll
        for (int k = 0; k < 9; k++) a += p1[k] * w[9 + k];
#pragma unroll
        for (int k = 0; k < 9; k++) a += p2[k] * w[18 + k];
        out[zz * 256 + tid] = a;
#pragma unroll
        for (int k = 0; k < 9; k++) { p0[k] = p1[k]; p1[k] = p2[k]; }
    }
}

// ---------------------------------------------------------------------------
extern "C" void kernel_launch(void* const* d_in, const int* in_sizes, int n_in,
                              void* d_out, int out_size)
{
    const float* query = (const float*)d_in[0];
    const float* m0 = (const float*)d_in[1];
    const float* m1 = (const float*)d_in[2];
    const float* m2 = (const float*)d_in[3];
    const float* m3 = (const float*)d_in[4];
    const int*   mask  = (const int*)d_in[5];
    const float* pw1_w = (const float*)d_in[6];
    const float* pw1_b = (const float*)d_in[7];
    const float* ln1_g = (const float*)d_in[8];
    const float* ln1_b = (const float*)d_in[9];
    const float* dw_w  = (const float*)d_in[10];
    const float* dw_b  = (const float*)d_in[11];
    const float* ln2_g = (const float*)d_in[12];
    const float* ln2_b = (const float*)d_in[13];
    const float* pw2_w = (const float*)d_in[14];
    const float* pw2_b = (const float*)d_in[15];
    const float* ln3_g = (const float*)d_in[16];
    const float* ln3_b = (const float*)d_in[17];
    float* out = (float*)d_out;

    float *y1, *y2, *qb, *kv, *xb, *at, *atp;
    cudaGetSymbolAddress((void**)&y1, g_y1);
    cudaGetSymbolAddress((void**)&y2, g_y2);
    cudaGetSymbolAddress((void**)&qb, g_q);
    cudaGetSymbolAddress((void**)&kv, g_KV);
    cudaGetSymbolAddress((void**)&xb, g_x);
    cudaGetSymbolAddress((void**)&at, g_at);
    cudaGetSymbolAddress((void**)&atp, g_atp);
    float* Kb = kv;
    float* Vt = kv + (long)Bb * C4L;

    cudaFuncSetAttribute(pw_v13, cudaFuncAttributeMaxDynamicSharedMemorySize, PW_SMEM);
    cudaFuncSetAttribute(qk_v10, cudaFuncAttributeMaxDynamicSharedMemorySize, QK_SMEM);
    cudaFuncSetAttribute(av_v9, cudaFuncAttributeMaxDynamicSharedMemorySize, AV_SMEM);

    // ---- weight prepack ----
    prep_w<<<20, 256>>>(pw1_w, pw2_w);

    // ---- blocks 0..8 (query + K/V maps) ----
    pw_v13<<<dim3(64, Bb, 9), 256, PW_SMEM>>>(
        query, m0, m1, m2, m3, /*imode=*/1, /*wofs=*/0,
        pw1_b, ln1_g, ln1_b, ln1_g, ln1_b, /*blk0=*/0,
        nullptr, y1, nullptr, /*omode=*/1, /*flags=*/2);
    dw_v3<<<dim3(Cch, Bb, 9), 256>>>(y1, y2, BCL, CL, dw_w, dw_b, 0);
    pw_v13<<<dim3(64, Bb, 9), 256, PW_SMEM>>>(
        y2, nullptr, nullptr, nullptr, nullptr, /*imode=*/2, /*wofs=*/10,
        pw2_b, ln2_g, ln2_b, ln3_g, ln3_b, /*blk0=*/0,
        nullptr, qb, kv, /*omode=*/2, /*flags=*/1);

    // ---- attention ----
    qk_v10<<<dim3(4, 4, 16), 256, QK_SMEM>>>(qb, Kb, atp);
    softmax_v6<<<Bb * 128, 128>>>(atp, at, mask);
    av_v9<<<dim3(64, Bb), 256, AV_SMEM>>>(at, Vt, xb);

    // ---- out_project (blk 9) + residual ----
    pw_v13<<<dim3(64, Bb, 1), 256, PW_SMEM>>>(
        xb, nullptr, nullptr, nullptr, nullptr, /*imode=*/0, /*wofs=*/0,
        pw1_b, ln1_g, ln1_b, ln1_g, ln1_b, /*blk0=*/9,
        nullptr, y1, nullptr, /*omode=*/0, /*flags=*/2);
    dw_v3<<<dim3(Cch, Bb, 1), 256>>>(y1, y2, BCL, CL, dw_w, dw_b, 9);
    pw_v13<<<dim3(64, Bb, 1), 256, PW_SMEM>>>(
        y2, nullptr, nullptr, nullptr, nullptr, /*imode=*/0, /*wofs=*/10,
        pw2_b, ln2_g, ln2_b, ln3_g, ln3_b, /*blk0=*/9,
        query, out, nullptr, /*omode=*/0, /*flags=*/1 | 4);
}